// round 10
// baseline (speedup 1.0000x reference)
#include <cuda_runtime.h>
#include <cuda_bf16.h>
#include <mma.h>
#include <cstdint>

using namespace nvcuda;

#define BB 32768
#define CC 1024
#define CH 256

typedef __nv_bfloat16 bf16;

// ---------------- device scratch (static, no allocation) ----------------
__device__ __align__(16) bf16  g_xn[(size_t)BB * CC];        // LN output, bf16
__device__ __align__(16) bf16  g_h1[(size_t)BB * CH];
__device__ __align__(16) bf16  g_t [(size_t)BB * CH];
__device__ __align__(16) bf16  g_h3[(size_t)BB * CH];

__device__ __align__(16) bf16  g_Wdg[1024 * 512];            // [Wd | Wg] bf16
__device__ __align__(16) float g_bdg[512];
__device__ __align__(16) bf16  g_W1b[256 * 256];
__device__ __align__(16) float g_Wvof[256 * 256];            // fp32 Wv@Wo
__device__ __align__(16) float g_bvo[256];
__device__ __align__(16) bf16  g_W23[256 * 256];             // W2 @ (Wv@Wo)
__device__ __align__(16) float g_b23[256];
__device__ __align__(16) bf16  g_Wu2[256 * 1024];            // Wu + (Wu@Wld)@Wlu
__device__ __align__(16) float g_bu2[1024];
__device__ __align__(16) float g_T[256 * 16];

// ---------------- helpers ----------------
__device__ __forceinline__ float gelu_tanh(float x) {
    float x3 = x * x * x;
    return 0.5f * x * (1.0f + tanhf(0.7978845608028654f * (x + 0.044715f * x3)));
}

__device__ __forceinline__ void cp16(uint32_t d, const void* s) {
    asm volatile("cp.async.cg.shared.global [%0], [%1], 16;\n" :: "r"(d), "l"(s));
}

// ---------------- prep kernels ----------------
__global__ void cvt_kernel(const float* __restrict__ src, bf16* __restrict__ dst, int n) {
    int i = blockIdx.x * 256 + threadIdx.x;
    if (i < n) dst[i] = __float2bfloat16(src[i]);
}

__global__ void prep_wdg(const float* __restrict__ Wd, const float* __restrict__ Wg) {
    int idx = blockIdx.x * 256 + threadIdx.x;   // < 1024*512
    int k = idx >> 9, j = idx & 511;
    float v = (j < 256) ? Wd[k * 256 + j] : Wg[k * 256 + (j - 256)];
    g_Wdg[idx] = __float2bfloat16(v);
}

__global__ void prep_bdg(const float* __restrict__ bd, const float* __restrict__ bg) {
    int j = threadIdx.x;  // 512 threads
    g_bdg[j] = (j < 256) ? bd[j] : bg[j - 256];
}

__global__ void prep_wvo(const float* __restrict__ Wv, const float* __restrict__ Wo,
                         const float* __restrict__ bv, const float* __restrict__ bo) {
    __shared__ float row[256];
    int i = blockIdx.x, j = threadIdx.x;
    row[j] = Wv[i * 256 + j];
    __syncthreads();
    float a0 = 0.f, a1 = 0.f, a2 = 0.f, a3 = 0.f;
    #pragma unroll 4
    for (int k = 0; k < 256; k += 4) {
        a0 += row[k + 0] * Wo[(k + 0) * 256 + j];
        a1 += row[k + 1] * Wo[(k + 1) * 256 + j];
        a2 += row[k + 2] * Wo[(k + 2) * 256 + j];
        a3 += row[k + 3] * Wo[(k + 3) * 256 + j];
    }
    g_Wvof[i * 256 + j] = (a0 + a1) + (a2 + a3);
    if (i == 0) {
        float b0 = 0.f, b1_ = 0.f;
        for (int k = 0; k < 256; k += 2) {
            b0  += bv[k] * Wo[k * 256 + j];
            b1_ += bv[k + 1] * Wo[(k + 1) * 256 + j];
        }
        g_bvo[j] = b0 + b1_ + bo[j];
    }
}

__global__ void prep_w2vo(const float* __restrict__ W2, const float* __restrict__ b2) {
    __shared__ float row[256];
    int i = blockIdx.x, j = threadIdx.x;
    row[j] = W2[i * 256 + j];
    __syncthreads();
    float a0 = 0.f, a1 = 0.f, a2 = 0.f, a3 = 0.f;
    #pragma unroll 4
    for (int k = 0; k < 256; k += 4) {
        a0 += row[k + 0] * g_Wvof[(k + 0) * 256 + j];
        a1 += row[k + 1] * g_Wvof[(k + 1) * 256 + j];
        a2 += row[k + 2] * g_Wvof[(k + 2) * 256 + j];
        a3 += row[k + 3] * g_Wvof[(k + 3) * 256 + j];
    }
    g_W23[i * 256 + j] = __float2bfloat16((a0 + a1) + (a2 + a3));
    if (i == 0) {
        float b0 = 0.f, b1_ = 0.f;
        for (int k = 0; k < 256; k += 2) {
            b0  += b2[k] * g_Wvof[k * 256 + j];
            b1_ += b2[k + 1] * g_Wvof[(k + 1) * 256 + j];
        }
        g_b23[j] = b0 + b1_ + g_bvo[j];
    }
}

__global__ void prep_T(const float* __restrict__ Wu, const float* __restrict__ Wld) {
    int i = blockIdx.x, t = threadIdx.x;
    int r = t & 15, seg = t >> 4;
    float acc = 0.f;
    int k0 = seg * 64;
    #pragma unroll 4
    for (int k = k0; k < k0 + 64; k++) acc += Wu[i * 1024 + k] * Wld[k * 16 + r];
    __shared__ float red[256];
    red[t] = acc;
    __syncthreads();
    if (seg == 0) {
        float s = 0.f;
        #pragma unroll
        for (int q = 0; q < 16; q++) s += red[q * 16 + r];
        g_T[i * 16 + r] = s;
    }
}

__global__ void prep_wu2(const float* __restrict__ Wu, const float* __restrict__ Wlu) {
    int i = blockIdx.x;
    int j = blockIdx.y * 256 + threadIdx.x;
    __shared__ float Ti[16];
    if (threadIdx.x < 16) Ti[threadIdx.x] = g_T[i * 16 + threadIdx.x];
    __syncthreads();
    float acc = Wu[i * 1024 + j];
    #pragma unroll
    for (int r = 0; r < 16; r++) acc += Ti[r] * Wlu[r * 1024 + j];
    g_Wu2[i * 1024 + j] = __float2bfloat16(acc);
}

__global__ void prep_bu2(const float* __restrict__ bu, const float* __restrict__ Wld,
                         const float* __restrict__ Wlu) {
    __shared__ float s[16];
    int t = threadIdx.x;
    if (t < 16) {
        float a = 0.f;
        for (int k = 0; k < 1024; k++) a += bu[k] * Wld[k * 16 + t];
        s[t] = a;
    }
    __syncthreads();
    float acc = bu[t];
    #pragma unroll
    for (int r = 0; r < 16; r++) acc += s[r] * Wlu[r * 1024 + t];
    g_bu2[t] = acc;
}

// ---------------- LayerNorm: one warp per row ----------------
__global__ void ln_kernel(const float* __restrict__ x, const float* __restrict__ gw,
                          const float* __restrict__ bw) {
    int warp = threadIdx.x >> 5, lane = threadIdx.x & 31;
    int row = blockIdx.x * 8 + warp;
    const float4* xr = (const float4*)(x + (size_t)row * CC);
    float4 v[8];
    float s = 0.f, q = 0.f;
    #pragma unroll
    for (int i = 0; i < 8; i++) {
        v[i] = xr[lane + 32 * i];
        s += v[i].x + v[i].y + v[i].z + v[i].w;
        q += v[i].x * v[i].x + v[i].y * v[i].y + v[i].z * v[i].z + v[i].w * v[i].w;
    }
    #pragma unroll
    for (int o = 16; o; o >>= 1) {
        s += __shfl_xor_sync(0xffffffffu, s, o);
        q += __shfl_xor_sync(0xffffffffu, q, o);
    }
    float mu = s * (1.0f / 1024.0f);
    float var = q * (1.0f / 1024.0f) - mu * mu;
    float rs = rsqrtf(var + 1e-5f);
    uint2* dst = (uint2*)(g_xn + (size_t)row * CC);
    const float4* g4 = (const float4*)gw;
    const float4* b4 = (const float4*)bw;
    #pragma unroll
    for (int i = 0; i < 8; i++) {
        int idx = lane + 32 * i;
        float4 gg = g4[idx], bb = b4[idx];
        float y0 = (v[i].x - mu) * rs * gg.x + bb.x;
        float y1 = (v[i].y - mu) * rs * gg.y + bb.y;
        float y2 = (v[i].z - mu) * rs * gg.z + bb.z;
        float y3 = (v[i].w - mu) * rs * gg.w + bb.w;
        __nv_bfloat162 lo = __floats2bfloat162_rn(y0, y1);
        __nv_bfloat162 hi = __floats2bfloat162_rn(y2, y3);
        uint2 u;
        u.x = *reinterpret_cast<unsigned*>(&lo);
        u.y = *reinterpret_cast<unsigned*>(&hi);
        dst[idx] = u;
    }
}

// ================= pipelined smem GEMM machinery (proven gemm2s recipe) =========
// 512 threads, 2-stage cp.async, per-warp accumulators limited to 4 fragments.
#define AS2 5120    // 128 * 40 bf16 per A stage
#define BS2 4352    // 32 * 136 bf16 per B stage

// ---------------- gemm1 fused with GLU + depthwise affine, pipelined ----------
// CTA: 128 rows x 64 output cols. Each warp (mw 0-3, nw 0-3) computes a 32x16
// block of BOTH d (Wdg col base+c) and g (Wdg col 256+base+c): 4 accum frags.
__global__ void __launch_bounds__(512)
gemm1s_glu_kernel(const float* __restrict__ dw_w, const float* __restrict__ dw_b) {
    __shared__ __align__(16) char sm[37888];
    bf16* sA = reinterpret_cast<bf16*>(sm);
    bf16* sB = reinterpret_cast<bf16*>(sm + 2 * AS2 * 2);
    uint32_t sA_u = (uint32_t)__cvta_generic_to_shared(sA);
    uint32_t sB_u = (uint32_t)__cvta_generic_to_shared(sB);

    int tid = threadIdx.x;
    int warp = tid >> 5, lane = tid & 31;
    int mw = warp >> 2, nw = warp & 3;
    int row0 = blockIdx.y * 128;
    int base = blockIdx.x * 64;                 // actual d-col base (g at 256+)

    wmma::fragment<wmma::accumulator, 16, 16, 16, float> cd[2], cg[2];
    #pragma unroll
    for (int i = 0; i < 2; i++) { wmma::fill_fragment(cd[i], 0.0f); wmma::fill_fragment(cg[i], 0.0f); }

    int ar = tid >> 2, ac = (tid & 3) << 3;     // A: 128 x 32
    int br = tid >> 4, bc = (tid & 15) << 3;    // B: 32 x 128 virtual (d | g)
    int bcol = (bc < 64) ? (base + bc) : (256 + base + (bc - 64));

    auto load_tile = [&](int stage, int k0) {
        cp16(sA_u + (stage * AS2 + ar * 40 + ac) * 2,
             g_xn + (size_t)(row0 + ar) * 1024 + k0 + ac);
        cp16(sB_u + (stage * BS2 + br * 136 + bc) * 2,
             g_Wdg + (size_t)(k0 + br) * 512 + bcol);
        asm volatile("cp.async.commit_group;\n");
    };

    load_tile(0, 0);
    const int KT = 32;                          // K = 1024 / 32
    for (int kt = 0; kt < KT; kt++) {
        int cur = kt & 1;
        if (kt + 1 < KT) {
            load_tile(cur ^ 1, (kt + 1) * 32);
            asm volatile("cp.async.wait_group 1;\n");
        } else {
            asm volatile("cp.async.wait_group 0;\n");
        }
        __syncthreads();
        #pragma unroll
        for (int ks = 0; ks < 2; ks++) {
            wmma::fragment<wmma::matrix_a, 16, 16, 16, bf16, wmma::row_major> a0, a1;
            wmma::fragment<wmma::matrix_b, 16, 16, 16, bf16, wmma::row_major> bd_, bg_;
            const bf16* pa = sA + cur * AS2 + (mw * 32) * 40 + ks * 16;
            wmma::load_matrix_sync(a0, pa, 40);
            wmma::load_matrix_sync(a1, pa + 16 * 40, 40);
            const bf16* pb = sB + cur * BS2 + (ks * 16) * 136;
            wmma::load_matrix_sync(bd_, pb + nw * 16, 136);
            wmma::load_matrix_sync(bg_, pb + 64 + nw * 16, 136);
            wmma::mma_sync(cd[0], a0, bd_, cd[0]);
            wmma::mma_sync(cd[1], a1, bd_, cd[1]);
            wmma::mma_sync(cg[0], a0, bg_, cg[0]);
            wmma::mma_sync(cg[1], a1, bg_, cg[1]);
        }
        __syncthreads();
    }

    // epilogue: per-warp private smem patch (16x17 d + 16x17 g floats)
    float* sW = reinterpret_cast<float*>(sm) + warp * 544;
    int gcol = base + nw * 16 + ((lane & 1) << 3);
    float4 bd4a = *(const float4*)(g_bdg + gcol);
    float4 bd4b = *(const float4*)(g_bdg + gcol + 4);
    float4 bg4a = *(const float4*)(g_bdg + 256 + gcol);
    float4 bg4b = *(const float4*)(g_bdg + 256 + gcol + 4);
    float4 w4a  = *(const float4*)(dw_w + gcol);
    float4 w4b  = *(const float4*)(dw_w + gcol + 4);
    float4 db4a = *(const float4*)(dw_b + gcol);
    float4 db4b = *(const float4*)(dw_b + gcol + 4);
    float bdv[8] = {bd4a.x, bd4a.y, bd4a.z, bd4a.w, bd4b.x, bd4b.y, bd4b.z, bd4b.w};
    float bgv[8] = {bg4a.x, bg4a.y, bg4a.z, bg4a.w, bg4b.x, bg4b.y, bg4b.z, bg4b.w};
    float wv [8] = {w4a.x,  w4a.y,  w4a.z,  w4a.w,  w4b.x,  w4b.y,  w4b.z,  w4b.w};
    float dbv[8] = {db4a.x, db4a.y, db4a.z, db4a.w, db4b.x, db4b.y, db4b.z, db4b.w};

    #pragma unroll
    for (int i = 0; i < 2; i++) {
        __syncwarp();
        wmma::store_matrix_sync(sW, cd[i], 17, wmma::mem_row_major);
        wmma::store_matrix_sync(sW + 272, cg[i], 17, wmma::mem_row_major);
        __syncwarp();
        int r = lane >> 1;
        int colh = (lane & 1) << 3;
        int grow = row0 + mw * 32 + i * 16 + r;
        float h[8];
        #pragma unroll
        for (int q = 0; q < 8; q++) {
            float d = sW[r * 17 + colh + q] + bdv[q];
            float g = sW[272 + r * 17 + colh + q] + bgv[q];
            h[q] = d * (1.0f / (1.0f + __expf(-g))) * wv[q] + dbv[q];
        }
        __nv_bfloat162 p0 = __floats2bfloat162_rn(h[0], h[1]);
        __nv_bfloat162 p1 = __floats2bfloat162_rn(h[2], h[3]);
        __nv_bfloat162 p2 = __floats2bfloat162_rn(h[4], h[5]);
        __nv_bfloat162 p3 = __floats2bfloat162_rn(h[6], h[7]);
        uint4 u;
        u.x = *reinterpret_cast<unsigned*>(&p0);
        u.y = *reinterpret_cast<unsigned*>(&p1);
        u.z = *reinterpret_cast<unsigned*>(&p2);
        u.w = *reinterpret_cast<unsigned*>(&p3);
        *(uint4*)(g_h1 + (size_t)grow * 256 + gcol) = u;
    }
}

// ---------------- generalized pipelined GEMM (gemm2s recipe) -------------------
// EPI: 0 = bias (bf16 out), 1 = bias+gelu (bf16 out), 2 = bias + residual mix (fp32 out)
template <int EPI, int N, int K>
__global__ void __launch_bounds__(512)
gemms_kernel(const bf16* __restrict__ A, const bf16* __restrict__ Bw,
             const float* __restrict__ bias, bf16* __restrict__ Cb,
             float* __restrict__ Cf, const float* __restrict__ xres) {
    __shared__ __align__(16) char sm[37888];
    bf16* sA = reinterpret_cast<bf16*>(sm);
    bf16* sB = reinterpret_cast<bf16*>(sm + 2 * AS2 * 2);
    uint32_t sA_u = (uint32_t)__cvta_generic_to_shared(sA);
    uint32_t sB_u = (uint32_t)__cvta_generic_to_shared(sB);

    int tid = threadIdx.x;
    int warp = tid >> 5, lane = tid & 31;
    int mw = warp >> 2, nw = warp & 3;
    int row0 = blockIdx.y * 128;
    int col0 = blockIdx.x * 128;

    wmma::fragment<wmma::accumulator, 16, 16, 16, float> c[2][2];
    #pragma unroll
    for (int i = 0; i < 2; i++)
        #pragma unroll
        for (int j = 0; j < 2; j++) wmma::fill_fragment(c[i][j], 0.0f);

    int ar = tid >> 2, ac = (tid & 3) << 3;
    int br = tid >> 4, bc = (tid & 15) << 3;

    auto load_tile = [&](int stage, int k0) {
        cp16(sA_u + (stage * AS2 + ar * 40 + ac) * 2,
             A + (size_t)(row0 + ar) * K + k0 + ac);
        cp16(sB_u + (stage * BS2 + br * 136 + bc) * 2,
             Bw + (size_t)(k0 + br) * N + col0 + bc);
        asm volatile("cp.async.commit_group;\n");
    };

    load_tile(0, 0);
    const int KT = K / 32;
    for (int kt = 0; kt < KT; kt++) {
        int cur = kt & 1;
        if (kt + 1 < KT) {
            load_tile(cur ^ 1, (kt + 1) * 32);
            asm volatile("cp.async.wait_group 1;\n");
        } else {
            asm volatile("cp.async.wait_group 0;\n");
        }
        __syncthreads();
        #pragma unroll
        for (int ks = 0; ks < 2; ks++) {
            wmma::fragment<wmma::matrix_a, 16, 16, 16, bf16, wmma::row_major> a0, a1;
            wmma::fragment<wmma::matrix_b, 16, 16, 16, bf16, wmma::row_major> b0, b1;
            const bf16* pa = sA + cur * AS2 + (mw * 32) * 40 + ks * 16;
            wmma::load_matrix_sync(a0, pa, 40);
            wmma::load_matrix_sync(a1, pa + 16 * 40, 40);
            const bf16* pb = sB + cur * BS2 + (ks * 16) * 136 + nw * 32;
            wmma::load_matrix_sync(b0, pb, 136);
            wmma::load_matrix_sync(b1, pb + 16, 136);
            wmma::mma_sync(c[0][0], a0, b0, c[0][0]);
            wmma::mma_sync(c[0][1], a0, b1, c[0][1]);
            wmma::mma_sync(c[1][0], a1, b0, c[1][0]);
            wmma::mma_sync(c[1][1], a1, b1, c[1][1]);
        }
        __syncthreads();
    }

    // epilogue: per-warp staging 32x18 floats
    float* sW = reinterpret_cast<float*>(sm) + warp * 576;
    #pragma unroll
    for (int j = 0; j < 2; j++) {
        __syncwarp();
        wmma::store_matrix_sync(sW, c[0][j], 18, wmma::mem_row_major);
        wmma::store_matrix_sync(sW + 16 * 18, c[1][j], 18, wmma::mem_row_major);
        __syncwarp();
        int r = lane;
        int grow = row0 + mw * 32 + r;
        int gcol = col0 + nw * 32 + j * 16;
        #pragma unroll
        for (int half = 0; half < 2; half++) {
            float v[8];
            #pragma unroll
            for (int q = 0; q < 8; q++)
                v[q] = sW[r * 18 + half * 8 + q] + bias[gcol + half * 8 + q];
            if (EPI == 1) {
                #pragma unroll
                for (int q = 0; q < 8; q++) v[q] = gelu_tanh(v[q]);
            }
            if (EPI == 2) {
                const float* xr = xres + (size_t)grow * N + gcol + half * 8;
                float4 x0 = *(const float4*)xr;
                float4 x1 = *(const float4*)(xr + 4);
                float4 o0, o1;
                o0.x = 0.5f * v[0] + 0.5f * x0.x;
                o0.y = 0.5f * v[1] + 0.5f * x0.y;
                o0.z = 0.5f * v[2] + 0.5f * x0.z;
                o0.w = 0.5f * v[3] + 0.5f * x0.w;
                o1.x = 0.5f * v[4] + 0.5f * x1.x;
                o1.y = 0.5f * v[5] + 0.5f * x1.y;
                o1.z = 0.5f * v[6] + 0.5f * x1.z;
                o1.w = 0.5f * v[7] + 0.5f * x1.w;
                float* op = Cf + (size_t)grow * N + gcol + half * 8;
                *(float4*)op = o0;
                *(float4*)(op + 4) = o1;
            } else {
                __nv_bfloat162 p0 = __floats2bfloat162_rn(v[0], v[1]);
                __nv_bfloat162 p1 = __floats2bfloat162_rn(v[2], v[3]);
                __nv_bfloat162 p2 = __floats2bfloat162_rn(v[4], v[5]);
                __nv_bfloat162 p3 = __floats2bfloat162_rn(v[6], v[7]);
                uint4 u;
                u.x = *reinterpret_cast<unsigned*>(&p0);
                u.y = *reinterpret_cast<unsigned*>(&p1);
                u.z = *reinterpret_cast<unsigned*>(&p2);
                u.w = *reinterpret_cast<unsigned*>(&p3);
                *(uint4*)(Cb + (size_t)grow * N + gcol + half * 8) = u;
            }
        }
    }
}

// ---------------- launcher ----------------
extern "C" void kernel_launch(void* const* d_in, const int* in_sizes, int n_in,
                              void* d_out, int out_size) {
    const float* x    = (const float*)d_in[0];
    const float* ln_g = (const float*)d_in[1];
    const float* ln_b = (const float*)d_in[2];
    const float* Wd   = (const float*)d_in[3];
    const float* bd   = (const float*)d_in[4];
    const float* Wg   = (const float*)d_in[5];
    const float* bg   = (const float*)d_in[6];
    const float* dw_w = (const float*)d_in[7];
    const float* dw_b = (const float*)d_in[8];
    const float* W1   = (const float*)d_in[9];
    const float* b1   = (const float*)d_in[10];
    const float* W2   = (const float*)d_in[11];
    const float* b2   = (const float*)d_in[12];
    // d_in[13..16] = Wq,bq,Wk,bk : dead (softmax over a single key == 1)
    const float* Wv   = (const float*)d_in[17];
    const float* bv   = (const float*)d_in[18];
    const float* Wo   = (const float*)d_in[19];
    const float* bo   = (const float*)d_in[20];
    const float* Wu   = (const float*)d_in[21];
    const float* bu   = (const float*)d_in[22];
    const float* Wld  = (const float*)d_in[23];
    const float* Wlu  = (const float*)d_in[24];
    float* out = (float*)d_out;

    prep_wdg<<<(1024 * 512) / 256, 256>>>(Wd, Wg);                    // 1
    prep_bdg<<<1, 512>>>(bd, bg);                                     // 2
    ln_kernel<<<BB / 8, 256>>>(x, ln_g, ln_b);                        // 3
    gemm1s_glu_kernel<<<dim3(4, BB / 128), 512>>>(dw_w, dw_b);        // 4 (ncu slot)
    cvt_kernel<<<(256 * 256 + 255) / 256, 256>>>(W1, g_W1b, 256*256); // 5
    gemms_kernel<1, 256, 256><<<dim3(2, BB / 128), 512>>>(            // 6 gemm2
        g_h1, g_W1b, b1, g_t, nullptr, nullptr);
    prep_wvo<<<256, 256>>>(Wv, Wo, bv, bo);                           // 7
    prep_w2vo<<<256, 256>>>(W2, b2);                                  // 8
    gemms_kernel<0, 256, 256><<<dim3(2, BB / 128), 512>>>(            // 9 gemm3
        g_t, g_W23, g_b23, g_h3, nullptr, nullptr);
    prep_T<<<256, 256>>>(Wu, Wld);                                    // 10
    prep_wu2<<<dim3(256, 4), 256>>>(Wu, Wlu);                         // 11
    prep_bu2<<<1, 1024>>>(bu, Wld, Wlu);                              // 12
    gemms_kernel<2, 1024, 256><<<dim3(8, BB / 128), 512>>>(           // 13 gemm5
        g_h3, g_Wu2, g_bu2, nullptr, out, x);
}

// round 11
// speedup vs baseline: 1.0813x; 1.0813x over previous
#include <cuda_runtime.h>
#include <cuda_bf16.h>
#include <mma.h>
#include <cstdint>

using namespace nvcuda;

#define BB 32768
#define CC 1024
#define CH 256

typedef __nv_bfloat16 bf16;

// ---------------- device scratch (static, no allocation) ----------------
__device__ __align__(16) bf16  g_xn[(size_t)BB * CC];        // LN output, bf16
__device__ __align__(16) bf16  g_h1[(size_t)BB * CH];
__device__ __align__(16) bf16  g_t [(size_t)BB * CH];
__device__ __align__(16) bf16  g_h3[(size_t)BB * CH];

__device__ __align__(16) bf16  g_Wdg[1024 * 512];            // [Wd | Wg] bf16
__device__ __align__(16) float g_bdg[512];
__device__ __align__(16) bf16  g_W1b[256 * 256];
__device__ __align__(16) float g_Wvof[256 * 256];            // fp32 Wv@Wo
__device__ __align__(16) float g_bvo[256];
__device__ __align__(16) bf16  g_W23[256 * 256];             // W2 @ (Wv@Wo)
__device__ __align__(16) float g_b23[256];
__device__ __align__(16) bf16  g_Wu2[256 * 1024];            // Wu + (Wu@Wld)@Wlu
__device__ __align__(16) float g_bu2[1024];
__device__ __align__(16) float g_T[256 * 16];

// ---------------- helpers ----------------
__device__ __forceinline__ float gelu_tanh(float x) {
    float x3 = x * x * x;
    return 0.5f * x * (1.0f + tanhf(0.7978845608028654f * (x + 0.044715f * x3)));
}

__device__ __forceinline__ void cp16(uint32_t d, const void* s) {
    asm volatile("cp.async.cg.shared.global [%0], [%1], 16;\n" :: "r"(d), "l"(s));
}

// ---------------- prep kernels ----------------
__global__ void cvt_kernel(const float* __restrict__ src, bf16* __restrict__ dst, int n) {
    int i = blockIdx.x * 256 + threadIdx.x;
    if (i < n) dst[i] = __float2bfloat16(src[i]);
}

__global__ void prep_wdg(const float* __restrict__ Wd, const float* __restrict__ Wg) {
    int idx = blockIdx.x * 256 + threadIdx.x;   // < 1024*512
    int k = idx >> 9, j = idx & 511;
    float v = (j < 256) ? Wd[k * 256 + j] : Wg[k * 256 + (j - 256)];
    g_Wdg[idx] = __float2bfloat16(v);
}

__global__ void prep_bdg(const float* __restrict__ bd, const float* __restrict__ bg) {
    int j = threadIdx.x;  // 512 threads
    g_bdg[j] = (j < 256) ? bd[j] : bg[j - 256];
}

__global__ void prep_wvo(const float* __restrict__ Wv, const float* __restrict__ Wo,
                         const float* __restrict__ bv, const float* __restrict__ bo) {
    __shared__ float row[256];
    int i = blockIdx.x, j = threadIdx.x;
    row[j] = Wv[i * 256 + j];
    __syncthreads();
    float a0 = 0.f, a1 = 0.f, a2 = 0.f, a3 = 0.f;
    #pragma unroll 4
    for (int k = 0; k < 256; k += 4) {
        a0 += row[k + 0] * Wo[(k + 0) * 256 + j];
        a1 += row[k + 1] * Wo[(k + 1) * 256 + j];
        a2 += row[k + 2] * Wo[(k + 2) * 256 + j];
        a3 += row[k + 3] * Wo[(k + 3) * 256 + j];
    }
    g_Wvof[i * 256 + j] = (a0 + a1) + (a2 + a3);
    if (i == 0) {
        float b0 = 0.f, b1_ = 0.f;
        for (int k = 0; k < 256; k += 2) {
            b0  += bv[k] * Wo[k * 256 + j];
            b1_ += bv[k + 1] * Wo[(k + 1) * 256 + j];
        }
        g_bvo[j] = b0 + b1_ + bo[j];
    }
}

__global__ void prep_w2vo(const float* __restrict__ W2, const float* __restrict__ b2) {
    __shared__ float row[256];
    int i = blockIdx.x, j = threadIdx.x;
    row[j] = W2[i * 256 + j];
    __syncthreads();
    float a0 = 0.f, a1 = 0.f, a2 = 0.f, a3 = 0.f;
    #pragma unroll 4
    for (int k = 0; k < 256; k += 4) {
        a0 += row[k + 0] * g_Wvof[(k + 0) * 256 + j];
        a1 += row[k + 1] * g_Wvof[(k + 1) * 256 + j];
        a2 += row[k + 2] * g_Wvof[(k + 2) * 256 + j];
        a3 += row[k + 3] * g_Wvof[(k + 3) * 256 + j];
    }
    g_W23[i * 256 + j] = __float2bfloat16((a0 + a1) + (a2 + a3));
    if (i == 0) {
        float b0 = 0.f, b1_ = 0.f;
        for (int k = 0; k < 256; k += 2) {
            b0  += b2[k] * g_Wvof[k * 256 + j];
            b1_ += b2[k + 1] * g_Wvof[(k + 1) * 256 + j];
        }
        g_b23[j] = b0 + b1_ + g_bvo[j];
    }
}

__global__ void prep_T(const float* __restrict__ Wu, const float* __restrict__ Wld) {
    int i = blockIdx.x, t = threadIdx.x;
    int r = t & 15, seg = t >> 4;
    float acc = 0.f;
    int k0 = seg * 64;
    #pragma unroll 4
    for (int k = k0; k < k0 + 64; k++) acc += Wu[i * 1024 + k] * Wld[k * 16 + r];
    __shared__ float red[256];
    red[t] = acc;
    __syncthreads();
    if (seg == 0) {
        float s = 0.f;
        #pragma unroll
        for (int q = 0; q < 16; q++) s += red[q * 16 + r];
        g_T[i * 16 + r] = s;
    }
}

__global__ void prep_wu2(const float* __restrict__ Wu, const float* __restrict__ Wlu) {
    int i = blockIdx.x;
    int j = blockIdx.y * 256 + threadIdx.x;
    __shared__ float Ti[16];
    if (threadIdx.x < 16) Ti[threadIdx.x] = g_T[i * 16 + threadIdx.x];
    __syncthreads();
    float acc = Wu[i * 1024 + j];
    #pragma unroll
    for (int r = 0; r < 16; r++) acc += Ti[r] * Wlu[r * 1024 + j];
    g_Wu2[i * 1024 + j] = __float2bfloat16(acc);
}

__global__ void prep_bu2(const float* __restrict__ bu, const float* __restrict__ Wld,
                         const float* __restrict__ Wlu) {
    __shared__ float s[16];
    int t = threadIdx.x;
    if (t < 16) {
        float a = 0.f;
        for (int k = 0; k < 1024; k++) a += bu[k] * Wld[k * 16 + t];
        s[t] = a;
    }
    __syncthreads();
    float acc = bu[t];
    #pragma unroll
    for (int r = 0; r < 16; r++) acc += s[r] * Wlu[r * 1024 + t];
    g_bu2[t] = acc;
}

// ---------------- LayerNorm: one warp per row ----------------
__global__ void ln_kernel(const float* __restrict__ x, const float* __restrict__ gw,
                          const float* __restrict__ bw) {
    int warp = threadIdx.x >> 5, lane = threadIdx.x & 31;
    int row = blockIdx.x * 8 + warp;
    const float4* xr = (const float4*)(x + (size_t)row * CC);
    float4 v[8];
    float s = 0.f, q = 0.f;
    #pragma unroll
    for (int i = 0; i < 8; i++) {
        v[i] = xr[lane + 32 * i];
        s += v[i].x + v[i].y + v[i].z + v[i].w;
        q += v[i].x * v[i].x + v[i].y * v[i].y + v[i].z * v[i].z + v[i].w * v[i].w;
    }
    #pragma unroll
    for (int o = 16; o; o >>= 1) {
        s += __shfl_xor_sync(0xffffffffu, s, o);
        q += __shfl_xor_sync(0xffffffffu, q, o);
    }
    float mu = s * (1.0f / 1024.0f);
    float var = q * (1.0f / 1024.0f) - mu * mu;
    float rs = rsqrtf(var + 1e-5f);
    uint2* dst = (uint2*)(g_xn + (size_t)row * CC);
    const float4* g4 = (const float4*)gw;
    const float4* b4 = (const float4*)bw;
    #pragma unroll
    for (int i = 0; i < 8; i++) {
        int idx = lane + 32 * i;
        float4 gg = g4[idx], bb = b4[idx];
        float y0 = (v[i].x - mu) * rs * gg.x + bb.x;
        float y1 = (v[i].y - mu) * rs * gg.y + bb.y;
        float y2 = (v[i].z - mu) * rs * gg.z + bb.z;
        float y3 = (v[i].w - mu) * rs * gg.w + bb.w;
        __nv_bfloat162 lo = __floats2bfloat162_rn(y0, y1);
        __nv_bfloat162 hi = __floats2bfloat162_rn(y2, y3);
        uint2 u;
        u.x = *reinterpret_cast<unsigned*>(&lo);
        u.y = *reinterpret_cast<unsigned*>(&hi);
        dst[idx] = u;
    }
}

// ================= pipelined smem GEMM machinery =========
// 512 threads, 2-stage cp.async, 4 accumulator fragments per warp (proven fast),
// CTA-wide coalesced epilogue (proven from the direct body).
#define AS2 5120    // 128 * 40 bf16 per A stage
#define BS2 4352    // 32 * 136 bf16 per B stage
#define SMEM_BYTES 37888

// ---------------- gemm1 fused with GLU + depthwise affine, pipelined ----------
// CTA: 128 rows x 64 output cols (d at Wdg[base..], g at Wdg[256+base..]).
__global__ void __launch_bounds__(512)
gemm1s_glu_kernel(const float* __restrict__ dw_w, const float* __restrict__ dw_b) {
    __shared__ __align__(16) char sm[SMEM_BYTES];
    bf16* sA = reinterpret_cast<bf16*>(sm);
    bf16* sB = reinterpret_cast<bf16*>(sm + 2 * AS2 * 2);
    uint32_t sA_u = (uint32_t)__cvta_generic_to_shared(sA);
    uint32_t sB_u = (uint32_t)__cvta_generic_to_shared(sB);

    int tid = threadIdx.x;
    int warp = tid >> 5;
    int mw = warp >> 2, nw = warp & 3;
    int row0 = blockIdx.y * 128;
    int base = blockIdx.x * 64;                 // d-col base (g at 256+base)

    wmma::fragment<wmma::accumulator, 16, 16, 16, float> cd[2], cg[2];
    #pragma unroll
    for (int i = 0; i < 2; i++) { wmma::fill_fragment(cd[i], 0.0f); wmma::fill_fragment(cg[i], 0.0f); }

    int ar = tid >> 2, ac = (tid & 3) << 3;     // A: 128 x 32
    int br = tid >> 4, bc = (tid & 15) << 3;    // B: 32 x 128 virtual (d | g)
    int bcol = (bc < 64) ? (base + bc) : (256 + base + (bc - 64));

    auto load_tile = [&](int stage, int k0) {
        cp16(sA_u + (stage * AS2 + ar * 40 + ac) * 2,
             g_xn + (size_t)(row0 + ar) * 1024 + k0 + ac);
        cp16(sB_u + (stage * BS2 + br * 136 + bc) * 2,
             g_Wdg + (size_t)(k0 + br) * 512 + bcol);
        asm volatile("cp.async.commit_group;\n");
    };

    load_tile(0, 0);
    const int KT = 32;                          // K = 1024 / 32
    for (int kt = 0; kt < KT; kt++) {
        int cur = kt & 1;
        if (kt + 1 < KT) {
            load_tile(cur ^ 1, (kt + 1) * 32);
            asm volatile("cp.async.wait_group 1;\n");
        } else {
            asm volatile("cp.async.wait_group 0;\n");
        }
        __syncthreads();
        #pragma unroll
        for (int ks = 0; ks < 2; ks++) {
            wmma::fragment<wmma::matrix_a, 16, 16, 16, bf16, wmma::row_major> a0, a1;
            wmma::fragment<wmma::matrix_b, 16, 16, 16, bf16, wmma::row_major> bd_, bg_;
            const bf16* pa = sA + cur * AS2 + (mw * 32) * 40 + ks * 16;
            wmma::load_matrix_sync(a0, pa, 40);
            wmma::load_matrix_sync(a1, pa + 16 * 40, 40);
            const bf16* pb = sB + cur * BS2 + (ks * 16) * 136;
            wmma::load_matrix_sync(bd_, pb + nw * 16, 136);
            wmma::load_matrix_sync(bg_, pb + 64 + nw * 16, 136);
            wmma::mma_sync(cd[0], a0, bd_, cd[0]);
            wmma::mma_sync(cd[1], a1, bd_, cd[1]);
            wmma::mma_sync(cg[0], a0, bg_, cg[0]);
            wmma::mma_sync(cg[1], a1, bg_, cg[1]);
        }
        __syncthreads();
    }

    // ---- CTA-wide coalesced epilogue: two row-strip passes ----
    // Pass i stages 64 compressed rows (srow = mw*16 + rr) x (64 d | 64 g) at ld 136.
    float* sC = reinterpret_cast<float*>(sm);
    #pragma unroll
    for (int i = 0; i < 2; i++) {
        __syncthreads();
        wmma::store_matrix_sync(sC + (mw * 16) * 136 + nw * 16,      cd[i], 136, wmma::mem_row_major);
        wmma::store_matrix_sync(sC + (mw * 16) * 136 + 68 + nw * 16, cg[i], 136, wmma::mem_row_major);
        __syncthreads();
        #pragma unroll
        for (int e = tid; e < 64 * 16; e += 512) {
            int r = e >> 4;
            int c4 = (e & 15) << 2;
            int grow = row0 + (r >> 4) * 32 + i * 16 + (r & 15);
            int gcol = base + c4;
            float4 bd4 = *(const float4*)(g_bdg + gcol);
            float4 bg4 = *(const float4*)(g_bdg + 256 + gcol);
            float4 w4  = *(const float4*)(dw_w + gcol);
            float4 db4 = *(const float4*)(dw_b + gcol);
            float d0 = sC[r * 136 + c4 + 0] + bd4.x;
            float d1 = sC[r * 136 + c4 + 1] + bd4.y;
            float d2 = sC[r * 136 + c4 + 2] + bd4.z;
            float d3 = sC[r * 136 + c4 + 3] + bd4.w;
            float q0 = sC[r * 136 + 68 + c4 + 0] + bg4.x;
            float q1 = sC[r * 136 + 68 + c4 + 1] + bg4.y;
            float q2 = sC[r * 136 + 68 + c4 + 2] + bg4.z;
            float q3 = sC[r * 136 + 68 + c4 + 3] + bg4.w;
            float h0 = d0 * (1.0f / (1.0f + __expf(-q0))) * w4.x + db4.x;
            float h1 = d1 * (1.0f / (1.0f + __expf(-q1))) * w4.y + db4.y;
            float h2 = d2 * (1.0f / (1.0f + __expf(-q2))) * w4.z + db4.z;
            float h3 = d3 * (1.0f / (1.0f + __expf(-q3))) * w4.w + db4.w;
            __nv_bfloat162 lo = __floats2bfloat162_rn(h0, h1);
            __nv_bfloat162 hi = __floats2bfloat162_rn(h2, h3);
            uint2 u;
            u.x = *reinterpret_cast<unsigned*>(&lo);
            u.y = *reinterpret_cast<unsigned*>(&hi);
            *(uint2*)(g_h1 + (size_t)grow * 256 + gcol) = u;
        }
    }
}

// ---------------- generalized pipelined GEMM -------------------
// EPI: 0 = bias (bf16 out), 1 = bias+gelu (bf16 out), 2 = bias + residual mix (fp32 out)
template <int EPI, int N, int K>
__global__ void __launch_bounds__(512)
gemms_kernel(const bf16* __restrict__ A, const bf16* __restrict__ Bw,
             const float* __restrict__ bias, bf16* __restrict__ Cb,
             float* __restrict__ Cf, const float* __restrict__ xres) {
    __shared__ __align__(16) char sm[SMEM_BYTES];
    bf16* sA = reinterpret_cast<bf16*>(sm);
    bf16* sB = reinterpret_cast<bf16*>(sm + 2 * AS2 * 2);
    uint32_t sA_u = (uint32_t)__cvta_generic_to_shared(sA);
    uint32_t sB_u = (uint32_t)__cvta_generic_to_shared(sB);

    int tid = threadIdx.x;
    int warp = tid >> 5;
    int mw = warp >> 2, nw = warp & 3;
    int row0 = blockIdx.y * 128;
    int col0 = blockIdx.x * 128;

    wmma::fragment<wmma::accumulator, 16, 16, 16, float> c[2][2];
    #pragma unroll
    for (int i = 0; i < 2; i++)
        #pragma unroll
        for (int j = 0; j < 2; j++) wmma::fill_fragment(c[i][j], 0.0f);

    int ar = tid >> 2, ac = (tid & 3) << 3;
    int br = tid >> 4, bc = (tid & 15) << 3;

    auto load_tile = [&](int stage, int k0) {
        cp16(sA_u + (stage * AS2 + ar * 40 + ac) * 2,
             A + (size_t)(row0 + ar) * K + k0 + ac);
        cp16(sB_u + (stage * BS2 + br * 136 + bc) * 2,
             Bw + (size_t)(k0 + br) * N + col0 + bc);
        asm volatile("cp.async.commit_group;\n");
    };

    load_tile(0, 0);
    const int KT = K / 32;
    for (int kt = 0; kt < KT; kt++) {
        int cur = kt & 1;
        if (kt + 1 < KT) {
            load_tile(cur ^ 1, (kt + 1) * 32);
            asm volatile("cp.async.wait_group 1;\n");
        } else {
            asm volatile("cp.async.wait_group 0;\n");
        }
        __syncthreads();
        #pragma unroll
        for (int ks = 0; ks < 2; ks++) {
            wmma::fragment<wmma::matrix_a, 16, 16, 16, bf16, wmma::row_major> a0, a1;
            wmma::fragment<wmma::matrix_b, 16, 16, 16, bf16, wmma::row_major> b0, b1;
            const bf16* pa = sA + cur * AS2 + (mw * 32) * 40 + ks * 16;
            wmma::load_matrix_sync(a0, pa, 40);
            wmma::load_matrix_sync(a1, pa + 16 * 40, 40);
            const bf16* pb = sB + cur * BS2 + (ks * 16) * 136 + nw * 32;
            wmma::load_matrix_sync(b0, pb, 136);
            wmma::load_matrix_sync(b1, pb + 16, 136);
            wmma::mma_sync(c[0][0], a0, b0, c[0][0]);
            wmma::mma_sync(c[0][1], a0, b1, c[0][1]);
            wmma::mma_sync(c[1][0], a1, b0, c[1][0]);
            wmma::mma_sync(c[1][1], a1, b1, c[1][1]);
        }
        __syncthreads();
    }

    // ---- CTA-wide coalesced epilogue: two row-strip passes over 64x128 ----
    // Pass i stages compressed rows (srow = mw*16 + rr) x 128 cols at ld 132.
    float* sC = reinterpret_cast<float*>(sm);
    #pragma unroll
    for (int i = 0; i < 2; i++) {
        __syncthreads();
        wmma::store_matrix_sync(sC + (mw * 16) * 132 + nw * 32,      c[i][0], 132, wmma::mem_row_major);
        wmma::store_matrix_sync(sC + (mw * 16) * 132 + nw * 32 + 16, c[i][1], 132, wmma::mem_row_major);
        __syncthreads();
        #pragma unroll
        for (int e = tid; e < 64 * 32; e += 512) {
            int r = e >> 5;
            int c4 = (e & 31) << 2;
            int grow = row0 + (r >> 4) * 32 + i * 16 + (r & 15);
            int gcol = col0 + c4;
            float4 bv = *(const float4*)(bias + gcol);
            float v0 = sC[r * 132 + c4 + 0] + bv.x;
            float v1 = sC[r * 132 + c4 + 1] + bv.y;
            float v2 = sC[r * 132 + c4 + 2] + bv.z;
            float v3 = sC[r * 132 + c4 + 3] + bv.w;
            if (EPI == 1) {
                v0 = gelu_tanh(v0); v1 = gelu_tanh(v1);
                v2 = gelu_tanh(v2); v3 = gelu_tanh(v3);
            }
            if (EPI == 2) {
                float4 xv = *(const float4*)(xres + (size_t)grow * N + gcol);
                float4 o;
                o.x = 0.5f * v0 + 0.5f * xv.x;
                o.y = 0.5f * v1 + 0.5f * xv.y;
                o.z = 0.5f * v2 + 0.5f * xv.z;
                o.w = 0.5f * v3 + 0.5f * xv.w;
                *(float4*)(Cf + (size_t)grow * N + gcol) = o;
            } else {
                __nv_bfloat162 lo = __floats2bfloat162_rn(v0, v1);
                __nv_bfloat162 hi = __floats2bfloat162_rn(v2, v3);
                uint2 u;
                u.x = *reinterpret_cast<unsigned*>(&lo);
                u.y = *reinterpret_cast<unsigned*>(&hi);
                *(uint2*)(Cb + (size_t)grow * N + gcol) = u;
            }
        }
    }
}

// ---------------- launcher ----------------
extern "C" void kernel_launch(void* const* d_in, const int* in_sizes, int n_in,
                              void* d_out, int out_size) {
    const float* x    = (const float*)d_in[0];
    const float* ln_g = (const float*)d_in[1];
    const float* ln_b = (const float*)d_in[2];
    const float* Wd   = (const float*)d_in[3];
    const float* bd   = (const float*)d_in[4];
    const float* Wg   = (const float*)d_in[5];
    const float* bg   = (const float*)d_in[6];
    const float* dw_w = (const float*)d_in[7];
    const float* dw_b = (const float*)d_in[8];
    const float* W1   = (const float*)d_in[9];
    const float* b1   = (const float*)d_in[10];
    const float* W2   = (const float*)d_in[11];
    const float* b2   = (const float*)d_in[12];
    // d_in[13..16] = Wq,bq,Wk,bk : dead (softmax over a single key == 1)
    const float* Wv   = (const float*)d_in[17];
    const float* bv   = (const float*)d_in[18];
    const float* Wo   = (const float*)d_in[19];
    const float* bo   = (const float*)d_in[20];
    const float* Wu   = (const float*)d_in[21];
    const float* bu   = (const float*)d_in[22];
    const float* Wld  = (const float*)d_in[23];
    const float* Wlu  = (const float*)d_in[24];
    float* out = (float*)d_out;

    prep_wdg<<<(1024 * 512) / 256, 256>>>(Wd, Wg);                    // 1
    prep_bdg<<<1, 512>>>(bd, bg);                                     // 2
    ln_kernel<<<BB / 8, 256>>>(x, ln_g, ln_b);                        // 3
    gemm1s_glu_kernel<<<dim3(4, BB / 128), 512>>>(dw_w, dw_b);        // 4 (ncu slot)
    cvt_kernel<<<(256 * 256 + 255) / 256, 256>>>(W1, g_W1b, 256*256); // 5
    gemms_kernel<1, 256, 256><<<dim3(2, BB / 128), 512>>>(            // 6 gemm2
        g_h1, g_W1b, b1, g_t, nullptr, nullptr);
    prep_wvo<<<256, 256>>>(Wv, Wo, bv, bo);                           // 7
    prep_w2vo<<<256, 256>>>(W2, b2);                                  // 8
    gemms_kernel<0, 256, 256><<<dim3(2, BB / 128), 512>>>(            // 9 gemm3
        g_t, g_W23, g_b23, g_h3, nullptr, nullptr);
    prep_T<<<256, 256>>>(Wu, Wld);                                    // 10
    prep_wu2<<<dim3(256, 4), 256>>>(Wu, Wlu);                         // 11
    prep_bu2<<<1, 1024>>>(bu, Wld, Wlu);                              // 12
    gemms_kernel<2, 1024, 256><<<dim3(8, BB / 128), 512>>>(           // 13 gemm5
        g_h3, g_Wu2, g_bu2, nullptr, out, x);
}

// round 12
// speedup vs baseline: 6.2212x; 5.7533x over previous
#include <cuda_runtime.h>
#include <cuda_bf16.h>
#include <mma.h>
#include <cstdint>

using namespace nvcuda;

#define BB 32768
#define CC 1024
#define CH 256

typedef __nv_bfloat16 bf16;

// ---------------- device scratch (static, no allocation) ----------------
__device__ __align__(16) bf16  g_xn[(size_t)BB * CC];        // LN output, bf16
__device__ __align__(16) bf16  g_h1[(size_t)BB * CH];
__device__ __align__(16) bf16  g_t [(size_t)BB * CH];
__device__ __align__(16) bf16  g_h3[(size_t)BB * CH];

__device__ __align__(16) bf16  g_Wdg[1024 * 512];            // [Wd | Wg] bf16
__device__ __align__(16) float g_bdg[512];
__device__ __align__(16) bf16  g_W1b[256 * 256];
__device__ __align__(16) float g_Wvof[256 * 256];            // fp32 Wv@Wo
__device__ __align__(16) float g_bvo[256];
__device__ __align__(16) bf16  g_W23[256 * 256];             // W2 @ (Wv@Wo)
__device__ __align__(16) float g_b23[256];
__device__ __align__(16) bf16  g_Wu2[256 * 1024];            // Wu + (Wu@Wld)@Wlu
__device__ __align__(16) float g_bu2[1024];
__device__ __align__(16) float g_T[256 * 16];

// ---------------- helpers ----------------
__device__ __forceinline__ float gelu_tanh(float x) {
    float x3 = x * x * x;
    return 0.5f * x * (1.0f + tanhf(0.7978845608028654f * (x + 0.044715f * x3)));
}

__device__ __forceinline__ void cp16(uint32_t d, const void* s) {
    asm volatile("cp.async.cg.shared.global [%0], [%1], 16;\n" :: "r"(d), "l"(s));
}

// ---------------- prep kernels ----------------
__global__ void cvt_kernel(const float* __restrict__ src, bf16* __restrict__ dst, int n) {
    int i = blockIdx.x * 256 + threadIdx.x;
    if (i < n) dst[i] = __float2bfloat16(src[i]);
}

__global__ void prep_wdg(const float* __restrict__ Wd, const float* __restrict__ Wg) {
    int idx = blockIdx.x * 256 + threadIdx.x;   // < 1024*512
    int k = idx >> 9, j = idx & 511;
    float v = (j < 256) ? Wd[k * 256 + j] : Wg[k * 256 + (j - 256)];
    g_Wdg[idx] = __float2bfloat16(v);
}

__global__ void prep_bdg(const float* __restrict__ bd, const float* __restrict__ bg) {
    int j = threadIdx.x;  // 512 threads
    g_bdg[j] = (j < 256) ? bd[j] : bg[j - 256];
}

__global__ void prep_wvo(const float* __restrict__ Wv, const float* __restrict__ Wo,
                         const float* __restrict__ bv, const float* __restrict__ bo) {
    __shared__ float row[256];
    int i = blockIdx.x, j = threadIdx.x;
    row[j] = Wv[i * 256 + j];
    __syncthreads();
    float a0 = 0.f, a1 = 0.f, a2 = 0.f, a3 = 0.f;
    #pragma unroll 4
    for (int k = 0; k < 256; k += 4) {
        a0 += row[k + 0] * Wo[(k + 0) * 256 + j];
        a1 += row[k + 1] * Wo[(k + 1) * 256 + j];
        a2 += row[k + 2] * Wo[(k + 2) * 256 + j];
        a3 += row[k + 3] * Wo[(k + 3) * 256 + j];
    }
    g_Wvof[i * 256 + j] = (a0 + a1) + (a2 + a3);
    if (i == 0) {
        float b0 = 0.f, b1_ = 0.f;
        for (int k = 0; k < 256; k += 2) {
            b0  += bv[k] * Wo[k * 256 + j];
            b1_ += bv[k + 1] * Wo[(k + 1) * 256 + j];
        }
        g_bvo[j] = b0 + b1_ + bo[j];
    }
}

__global__ void prep_w2vo(const float* __restrict__ W2, const float* __restrict__ b2) {
    __shared__ float row[256];
    int i = blockIdx.x, j = threadIdx.x;
    row[j] = W2[i * 256 + j];
    __syncthreads();
    float a0 = 0.f, a1 = 0.f, a2 = 0.f, a3 = 0.f;
    #pragma unroll 4
    for (int k = 0; k < 256; k += 4) {
        a0 += row[k + 0] * g_Wvof[(k + 0) * 256 + j];
        a1 += row[k + 1] * g_Wvof[(k + 1) * 256 + j];
        a2 += row[k + 2] * g_Wvof[(k + 2) * 256 + j];
        a3 += row[k + 3] * g_Wvof[(k + 3) * 256 + j];
    }
    g_W23[i * 256 + j] = __float2bfloat16((a0 + a1) + (a2 + a3));
    if (i == 0) {
        float b0 = 0.f, b1_ = 0.f;
        for (int k = 0; k < 256; k += 2) {
            b0  += b2[k] * g_Wvof[k * 256 + j];
            b1_ += b2[k + 1] * g_Wvof[(k + 1) * 256 + j];
        }
        g_b23[j] = b0 + b1_ + g_bvo[j];
    }
}

__global__ void prep_T(const float* __restrict__ Wu, const float* __restrict__ Wld) {
    int i = blockIdx.x, t = threadIdx.x;
    int r = t & 15, seg = t >> 4;
    float acc = 0.f;
    int k0 = seg * 64;
    #pragma unroll 4
    for (int k = k0; k < k0 + 64; k++) acc += Wu[i * 1024 + k] * Wld[k * 16 + r];
    __shared__ float red[256];
    red[t] = acc;
    __syncthreads();
    if (seg == 0) {
        float s = 0.f;
        #pragma unroll
        for (int q = 0; q < 16; q++) s += red[q * 16 + r];
        g_T[i * 16 + r] = s;
    }
}

__global__ void prep_wu2(const float* __restrict__ Wu, const float* __restrict__ Wlu) {
    int i = blockIdx.x;
    int j = blockIdx.y * 256 + threadIdx.x;
    __shared__ float Ti[16];
    if (threadIdx.x < 16) Ti[threadIdx.x] = g_T[i * 16 + threadIdx.x];
    __syncthreads();
    float acc = Wu[i * 1024 + j];
    #pragma unroll
    for (int r = 0; r < 16; r++) acc += Ti[r] * Wlu[r * 1024 + j];
    g_Wu2[i * 1024 + j] = __float2bfloat16(acc);
}

__global__ void prep_bu2(const float* __restrict__ bu, const float* __restrict__ Wld,
                         const float* __restrict__ Wlu) {
    __shared__ float s[16];
    int t = threadIdx.x;
    if (t < 16) {
        float a = 0.f;
        for (int k = 0; k < 1024; k++) a += bu[k] * Wld[k * 16 + t];
        s[t] = a;
    }
    __syncthreads();
    float acc = bu[t];
    #pragma unroll
    for (int r = 0; r < 16; r++) acc += s[r] * Wlu[r * 1024 + t];
    g_bu2[t] = acc;
}

// ---------------- LayerNorm: one warp per row ----------------
__global__ void ln_kernel(const float* __restrict__ x, const float* __restrict__ gw,
                          const float* __restrict__ bw) {
    int warp = threadIdx.x >> 5, lane = threadIdx.x & 31;
    int row = blockIdx.x * 8 + warp;
    const float4* xr = (const float4*)(x + (size_t)row * CC);
    float4 v[8];
    float s = 0.f, q = 0.f;
    #pragma unroll
    for (int i = 0; i < 8; i++) {
        v[i] = xr[lane + 32 * i];
        s += v[i].x + v[i].y + v[i].z + v[i].w;
        q += v[i].x * v[i].x + v[i].y * v[i].y + v[i].z * v[i].z + v[i].w * v[i].w;
    }
    #pragma unroll
    for (int o = 16; o; o >>= 1) {
        s += __shfl_xor_sync(0xffffffffu, s, o);
        q += __shfl_xor_sync(0xffffffffu, q, o);
    }
    float mu = s * (1.0f / 1024.0f);
    float var = q * (1.0f / 1024.0f) - mu * mu;
    float rs = rsqrtf(var + 1e-5f);
    uint2* dst = (uint2*)(g_xn + (size_t)row * CC);
    const float4* g4 = (const float4*)gw;
    const float4* b4 = (const float4*)bw;
    #pragma unroll
    for (int i = 0; i < 8; i++) {
        int idx = lane + 32 * i;
        float4 gg = g4[idx], bb = b4[idx];
        float y0 = (v[i].x - mu) * rs * gg.x + bb.x;
        float y1 = (v[i].y - mu) * rs * gg.y + bb.y;
        float y2 = (v[i].z - mu) * rs * gg.z + bb.z;
        float y3 = (v[i].w - mu) * rs * gg.w + bb.w;
        __nv_bfloat162 lo = __floats2bfloat162_rn(y0, y1);
        __nv_bfloat162 hi = __floats2bfloat162_rn(y2, y3);
        uint2 u;
        u.x = *reinterpret_cast<unsigned*>(&lo);
        u.y = *reinterpret_cast<unsigned*>(&hi);
        dst[idx] = u;
    }
}

// ================= pipelined smem GEMM machinery (measured-fast configs only) ===
#define AS2 5120    // 128 * 40 bf16 per A stage
#define BS2 4352    // 32 * 136 bf16 per B stage
#define SMEM_BYTES 37888

// ---------------- gemm1 fused with GLU + depthwise affine (197us measured) -----
__global__ void __launch_bounds__(512)
gemm1s_glu_kernel(const float* __restrict__ dw_w, const float* __restrict__ dw_b) {
    __shared__ __align__(16) char sm[SMEM_BYTES];
    bf16* sA = reinterpret_cast<bf16*>(sm);
    bf16* sB = reinterpret_cast<bf16*>(sm + 2 * AS2 * 2);
    uint32_t sA_u = (uint32_t)__cvta_generic_to_shared(sA);
    uint32_t sB_u = (uint32_t)__cvta_generic_to_shared(sB);

    int tid = threadIdx.x;
    int warp = tid >> 5;
    int mw = warp >> 2, nw = warp & 3;
    int row0 = blockIdx.y * 128;
    int base = blockIdx.x * 64;                 // d-col base (g at 256+base)

    wmma::fragment<wmma::accumulator, 16, 16, 16, float> cd[2], cg[2];
    #pragma unroll
    for (int i = 0; i < 2; i++) { wmma::fill_fragment(cd[i], 0.0f); wmma::fill_fragment(cg[i], 0.0f); }

    int ar = tid >> 2, ac = (tid & 3) << 3;     // A: 128 x 32
    int br = tid >> 4, bc = (tid & 15) << 3;    // B: 32 x 128 virtual (d | g)
    int bcol = (bc < 64) ? (base + bc) : (256 + base + (bc - 64));

    auto load_tile = [&](int stage, int k0) {
        cp16(sA_u + (stage * AS2 + ar * 40 + ac) * 2,
             g_xn + (size_t)(row0 + ar) * 1024 + k0 + ac);
        cp16(sB_u + (stage * BS2 + br * 136 + bc) * 2,
             g_Wdg + (size_t)(k0 + br) * 512 + bcol);
        asm volatile("cp.async.commit_group;\n");
    };

    load_tile(0, 0);
    const int KT = 32;                          // K = 1024 / 32
    for (int kt = 0; kt < KT; kt++) {
        int cur = kt & 1;
        if (kt + 1 < KT) {
            load_tile(cur ^ 1, (kt + 1) * 32);
            asm volatile("cp.async.wait_group 1;\n");
        } else {
            asm volatile("cp.async.wait_group 0;\n");
        }
        __syncthreads();
        #pragma unroll
        for (int ks = 0; ks < 2; ks++) {
            wmma::fragment<wmma::matrix_a, 16, 16, 16, bf16, wmma::row_major> a0, a1;
            wmma::fragment<wmma::matrix_b, 16, 16, 16, bf16, wmma::row_major> bd_, bg_;
            const bf16* pa = sA + cur * AS2 + (mw * 32) * 40 + ks * 16;
            wmma::load_matrix_sync(a0, pa, 40);
            wmma::load_matrix_sync(a1, pa + 16 * 40, 40);
            const bf16* pb = sB + cur * BS2 + (ks * 16) * 136;
            wmma::load_matrix_sync(bd_, pb + nw * 16, 136);
            wmma::load_matrix_sync(bg_, pb + 64 + nw * 16, 136);
            wmma::mma_sync(cd[0], a0, bd_, cd[0]);
            wmma::mma_sync(cd[1], a1, bd_, cd[1]);
            wmma::mma_sync(cg[0], a0, bg_, cg[0]);
            wmma::mma_sync(cg[1], a1, bg_, cg[1]);
        }
        __syncthreads();
    }

    // CTA-wide coalesced epilogue: two row-strip passes
    float* sC = reinterpret_cast<float*>(sm);
    #pragma unroll
    for (int i = 0; i < 2; i++) {
        __syncthreads();
        wmma::store_matrix_sync(sC + (mw * 16) * 136 + nw * 16,      cd[i], 136, wmma::mem_row_major);
        wmma::store_matrix_sync(sC + (mw * 16) * 136 + 68 + nw * 16, cg[i], 136, wmma::mem_row_major);
        __syncthreads();
        #pragma unroll
        for (int e = tid; e < 64 * 16; e += 512) {
            int r = e >> 4;
            int c4 = (e & 15) << 2;
            int grow = row0 + (r >> 4) * 32 + i * 16 + (r & 15);
            int gcol = base + c4;
            float4 bd4 = *(const float4*)(g_bdg + gcol);
            float4 bg4 = *(const float4*)(g_bdg + 256 + gcol);
            float4 w4  = *(const float4*)(dw_w + gcol);
            float4 db4 = *(const float4*)(dw_b + gcol);
            float d0 = sC[r * 136 + c4 + 0] + bd4.x;
            float d1 = sC[r * 136 + c4 + 1] + bd4.y;
            float d2 = sC[r * 136 + c4 + 2] + bd4.z;
            float d3 = sC[r * 136 + c4 + 3] + bd4.w;
            float q0 = sC[r * 136 + 68 + c4 + 0] + bg4.x;
            float q1 = sC[r * 136 + 68 + c4 + 1] + bg4.y;
            float q2 = sC[r * 136 + 68 + c4 + 2] + bg4.z;
            float q3 = sC[r * 136 + 68 + c4 + 3] + bg4.w;
            float h0 = d0 * (1.0f / (1.0f + __expf(-q0))) * w4.x + db4.x;
            float h1 = d1 * (1.0f / (1.0f + __expf(-q1))) * w4.y + db4.y;
            float h2 = d2 * (1.0f / (1.0f + __expf(-q2))) * w4.z + db4.z;
            float h3 = d3 * (1.0f / (1.0f + __expf(-q3))) * w4.w + db4.w;
            __nv_bfloat162 lo = __floats2bfloat162_rn(h0, h1);
            __nv_bfloat162 hi = __floats2bfloat162_rn(h2, h3);
            uint2 u;
            u.x = *reinterpret_cast<unsigned*>(&lo);
            u.y = *reinterpret_cast<unsigned*>(&hi);
            *(uint2*)(g_h1 + (size_t)(grow) * 256 + gcol) = u;
        }
    }
}

// ---------------- pipelined gemm2 (R8-proven shape: N=256, K=256, EPI=gelu) ----
__global__ void __launch_bounds__(512)
gemm2s_kernel(const float* __restrict__ b1) {
    __shared__ __align__(16) char sm[SMEM_BYTES];
    bf16* sA = reinterpret_cast<bf16*>(sm);
    bf16* sB = reinterpret_cast<bf16*>(sm + 2 * AS2 * 2);
    uint32_t sA_u = (uint32_t)__cvta_generic_to_shared(sA);
    uint32_t sB_u = (uint32_t)__cvta_generic_to_shared(sB);

    int tid = threadIdx.x;
    int warp = tid >> 5;
    int mw = warp >> 2, nw = warp & 3;
    int row0 = blockIdx.y * 128;
    int col0 = blockIdx.x * 128;

    wmma::fragment<wmma::accumulator, 16, 16, 16, float> c[2][2];
    #pragma unroll
    for (int i = 0; i < 2; i++)
        #pragma unroll
        for (int j = 0; j < 2; j++) wmma::fill_fragment(c[i][j], 0.0f);

    int ar = tid >> 2, ac = (tid & 3) << 3;
    int br = tid >> 4, bc = (tid & 15) << 3;

    auto load_tile = [&](int stage, int k0) {
        cp16(sA_u + (stage * AS2 + ar * 40 + ac) * 2,
             g_h1 + (size_t)(row0 + ar) * 256 + k0 + ac);
        cp16(sB_u + (stage * BS2 + br * 136 + bc) * 2,
             g_W1b + (size_t)(k0 + br) * 256 + col0 + bc);
        asm volatile("cp.async.commit_group;\n");
    };

    load_tile(0, 0);
    const int KT = 8;
    for (int kt = 0; kt < KT; kt++) {
        int cur = kt & 1;
        if (kt + 1 < KT) {
            load_tile(cur ^ 1, (kt + 1) * 32);
            asm volatile("cp.async.wait_group 1;\n");
        } else {
            asm volatile("cp.async.wait_group 0;\n");
        }
        __syncthreads();
        #pragma unroll
        for (int ks = 0; ks < 2; ks++) {
            wmma::fragment<wmma::matrix_a, 16, 16, 16, bf16, wmma::row_major> a0, a1;
            wmma::fragment<wmma::matrix_b, 16, 16, 16, bf16, wmma::row_major> b0, b1f;
            const bf16* pa = sA + cur * AS2 + (mw * 32) * 40 + ks * 16;
            wmma::load_matrix_sync(a0, pa, 40);
            wmma::load_matrix_sync(a1, pa + 16 * 40, 40);
            const bf16* pb = sB + cur * BS2 + (ks * 16) * 136 + nw * 32;
            wmma::load_matrix_sync(b0, pb, 136);
            wmma::load_matrix_sync(b1f, pb + 16, 136);
            wmma::mma_sync(c[0][0], a0, b0, c[0][0]);
            wmma::mma_sync(c[0][1], a0, b1f, c[0][1]);
            wmma::mma_sync(c[1][0], a1, b0, c[1][0]);
            wmma::mma_sync(c[1][1], a1, b1f, c[1][1]);
        }
        __syncthreads();
    }

    // CTA-wide coalesced epilogue
    float* sC = reinterpret_cast<float*>(sm);
    #pragma unroll
    for (int i = 0; i < 2; i++) {
        __syncthreads();
        wmma::store_matrix_sync(sC + (mw * 16) * 132 + nw * 32,      c[i][0], 132, wmma::mem_row_major);
        wmma::store_matrix_sync(sC + (mw * 16) * 132 + nw * 32 + 16, c[i][1], 132, wmma::mem_row_major);
        __syncthreads();
        #pragma unroll
        for (int e = tid; e < 64 * 32; e += 512) {
            int r = e >> 5;
            int c4 = (e & 31) << 2;
            int grow = row0 + (r >> 4) * 32 + i * 16 + (r & 15);
            int gcol = col0 + c4;
            float4 bv = *(const float4*)(b1 + gcol);
            float v0 = gelu_tanh(sC[r * 132 + c4 + 0] + bv.x);
            float v1 = gelu_tanh(sC[r * 132 + c4 + 1] + bv.y);
            float v2 = gelu_tanh(sC[r * 132 + c4 + 2] + bv.z);
            float v3 = gelu_tanh(sC[r * 132 + c4 + 3] + bv.w);
            __nv_bfloat162 lo = __floats2bfloat162_rn(v0, v1);
            __nv_bfloat162 hi = __floats2bfloat162_rn(v2, v3);
            uint2 u;
            u.x = *reinterpret_cast<unsigned*>(&lo);
            u.y = *reinterpret_cast<unsigned*>(&hi);
            *(uint2*)(g_t + (size_t)grow * 256 + gcol) = u;
        }
    }
}

// ---------------- direct-WMMA GEMM (R8-proven body), 64x128 block tile ---------
// Grid: (N/128, BB/64) column-fast for L2 reuse of A.
// EPI: 0 = bias (bf16 out), 2 = bias + residual mix (fp32 out)
template <int EPI, int N, int K>
__device__ __forceinline__ void gemm_body(const bf16* __restrict__ A,
                                          const bf16* __restrict__ Bw,
                                          const float* __restrict__ bias,
                                          bf16* __restrict__ Cb,
                                          float* __restrict__ Cf,
                                          const float* __restrict__ xres) {
    __shared__ float sC[64 * 132];
    int warp = threadIdx.x >> 5;
    int mw = warp >> 2, nw = warp & 3;
    int row0 = blockIdx.y * 64 + mw * 32;
    int col0 = blockIdx.x * 128 + nw * 32;

    wmma::fragment<wmma::accumulator, 16, 16, 16, float> c[2][2];
    #pragma unroll
    for (int i = 0; i < 2; i++)
        #pragma unroll
        for (int j = 0; j < 2; j++) wmma::fill_fragment(c[i][j], 0.0f);

    const bf16* Aptr = A + (size_t)row0 * K;
    #pragma unroll 4
    for (int k = 0; k < K; k += 16) {
        wmma::fragment<wmma::matrix_a, 16, 16, 16, bf16, wmma::row_major> a0, a1;
        wmma::fragment<wmma::matrix_b, 16, 16, 16, bf16, wmma::row_major> b0, b1;
        wmma::load_matrix_sync(a0, Aptr + k, K);
        wmma::load_matrix_sync(a1, Aptr + (size_t)16 * K + k, K);
        wmma::load_matrix_sync(b0, Bw + (size_t)k * N + col0, N);
        wmma::load_matrix_sync(b1, Bw + (size_t)k * N + col0 + 16, N);
        wmma::mma_sync(c[0][0], a0, b0, c[0][0]);
        wmma::mma_sync(c[0][1], a0, b1, c[0][1]);
        wmma::mma_sync(c[1][0], a1, b0, c[1][0]);
        wmma::mma_sync(c[1][1], a1, b1, c[1][1]);
    }

    #pragma unroll
    for (int i = 0; i < 2; i++)
        #pragma unroll
        for (int j = 0; j < 2; j++)
            wmma::store_matrix_sync(sC + (mw * 32 + 16 * i) * 132 + nw * 32 + 16 * j,
                                    c[i][j], 132, wmma::mem_row_major);
    __syncthreads();

    #pragma unroll
    for (int e = threadIdx.x; e < 64 * 32; e += 256) {
        int r = e >> 5;
        int c4 = (e & 31) << 2;
        int grow = blockIdx.y * 64 + r;
        int gcol = blockIdx.x * 128 + c4;
        float4 bv = *(const float4*)(bias + gcol);
        float v0 = sC[r * 132 + c4 + 0] + bv.x;
        float v1 = sC[r * 132 + c4 + 1] + bv.y;
        float v2 = sC[r * 132 + c4 + 2] + bv.z;
        float v3 = sC[r * 132 + c4 + 3] + bv.w;
        if (EPI == 2) {
            float4 xv = *(const float4*)(xres + (size_t)grow * N + gcol);
            float4 o;
            o.x = 0.5f * v0 + 0.5f * xv.x;
            o.y = 0.5f * v1 + 0.5f * xv.y;
            o.z = 0.5f * v2 + 0.5f * xv.z;
            o.w = 0.5f * v3 + 0.5f * xv.w;
            *(float4*)(Cf + (size_t)grow * N + gcol) = o;
        } else {
            __nv_bfloat162 lo = __floats2bfloat162_rn(v0, v1);
            __nv_bfloat162 hi = __floats2bfloat162_rn(v2, v3);
            uint2 u;
            u.x = *reinterpret_cast<unsigned*>(&lo);
            u.y = *reinterpret_cast<unsigned*>(&hi);
            *(uint2*)(Cb + (size_t)grow * N + gcol) = u;
        }
    }
}

__global__ void gemm3_kernel() {                                      // t@W23+b23
    gemm_body<0, 256, 256>(g_t, g_W23, g_b23, g_h3, nullptr, nullptr);
}
__global__ void gemm5_kernel(float* __restrict__ out, const float* __restrict__ x) {
    gemm_body<2, 1024, 256>(g_h3, g_Wu2, g_bu2, nullptr, out, x);     // up-proj + mix
}

// ---------------- launcher ----------------
extern "C" void kernel_launch(void* const* d_in, const int* in_sizes, int n_in,
                              void* d_out, int out_size) {
    const float* x    = (const float*)d_in[0];
    const float* ln_g = (const float*)d_in[1];
    const float* ln_b = (const float*)d_in[2];
    const float* Wd   = (const float*)d_in[3];
    const float* bd   = (const float*)d_in[4];
    const float* Wg   = (const float*)d_in[5];
    const float* bg   = (const float*)d_in[6];
    const float* dw_w = (const float*)d_in[7];
    const float* dw_b = (const float*)d_in[8];
    const float* W1   = (const float*)d_in[9];
    const float* b1   = (const float*)d_in[10];
    const float* W2   = (const float*)d_in[11];
    const float* b2   = (const float*)d_in[12];
    // d_in[13..16] = Wq,bq,Wk,bk : dead (softmax over a single key == 1)
    const float* Wv   = (const float*)d_in[17];
    const float* bv   = (const float*)d_in[18];
    const float* Wo   = (const float*)d_in[19];
    const float* bo   = (const float*)d_in[20];
    const float* Wu   = (const float*)d_in[21];
    const float* bu   = (const float*)d_in[22];
    const float* Wld  = (const float*)d_in[23];
    const float* Wlu  = (const float*)d_in[24];
    float* out = (float*)d_out;

    prep_wdg<<<(1024 * 512) / 256, 256>>>(Wd, Wg);                    // 1
    prep_bdg<<<1, 512>>>(bd, bg);                                     // 2
    ln_kernel<<<BB / 8, 256>>>(x, ln_g, ln_b);                        // 3
    gemm1s_glu_kernel<<<dim3(4, BB / 128), 512>>>(dw_w, dw_b);        // 4 (ncu slot)
    cvt_kernel<<<(256 * 256 + 255) / 256, 256>>>(W1, g_W1b, 256*256); // 5
    gemm2s_kernel<<<dim3(2, BB / 128), 512>>>(b1);                    // 6
    prep_wvo<<<256, 256>>>(Wv, Wo, bv, bo);                           // 7
    prep_w2vo<<<256, 256>>>(W2, b2);                                  // 8
    gemm3_kernel<<<dim3(2, BB / 64), 256>>>();                        // 9 (direct, proven)
    prep_T<<<256, 256>>>(Wu, Wld);                                    // 10
    prep_wu2<<<dim3(256, 4), 256>>>(Wu, Wlu);                         // 11
    prep_bu2<<<1, 1024>>>(bu, Wld, Wlu);                              // 12
    gemm5_kernel<<<dim3(8, BB / 64), 256>>>(out, x);                  // 13 (direct, proven)
}

// round 13
// speedup vs baseline: 6.6866x; 1.0748x over previous
#include <cuda_runtime.h>
#include <cuda_bf16.h>
#include <mma.h>
#include <cstdint>

using namespace nvcuda;

#define BB 32768
#define CC 1024
#define CH 256

typedef __nv_bfloat16 bf16;

// ---------------- device scratch (static, no allocation) ----------------
__device__ __align__(16) bf16  g_xn[(size_t)BB * CC];        // LN output, bf16
__device__ __align__(16) bf16  g_h1[(size_t)BB * CH];
__device__ __align__(16) bf16  g_t [(size_t)BB * CH];
__device__ __align__(16) bf16  g_h3[(size_t)BB * CH];

__device__ __align__(16) bf16  g_Wdg[1024 * 512];            // [Wd | Wg] bf16
__device__ __align__(16) float g_bdg[512];
__device__ __align__(16) bf16  g_W1b[256 * 256];
__device__ __align__(16) float g_Wvof[256 * 256];            // fp32 Wv@Wo
__device__ __align__(16) float g_bvo[256];
__device__ __align__(16) bf16  g_W23[256 * 256];             // W2 @ (Wv@Wo)
__device__ __align__(16) float g_b23[256];
__device__ __align__(16) bf16  g_Wu2[256 * 1024];            // Wu + (Wu@Wld)@Wlu
__device__ __align__(16) float g_bu2[1024];
__device__ __align__(16) float g_T[256 * 16];

// ---------------- helpers ----------------
__device__ __forceinline__ float gelu_tanh(float x) {
    float x3 = x * x * x;
    return 0.5f * x * (1.0f + tanhf(0.7978845608028654f * (x + 0.044715f * x3)));
}

__device__ __forceinline__ void cp16(uint32_t d, const void* s) {
    asm volatile("cp.async.cg.shared.global [%0], [%1], 16;\n" :: "r"(d), "l"(s));
}

// ---------------- prep kernels ----------------
__global__ void cvt_kernel(const float* __restrict__ src, bf16* __restrict__ dst, int n) {
    int i = blockIdx.x * 256 + threadIdx.x;
    if (i < n) dst[i] = __float2bfloat16(src[i]);
}

__global__ void prep_wdg(const float* __restrict__ Wd, const float* __restrict__ Wg) {
    int idx = blockIdx.x * 256 + threadIdx.x;   // < 1024*512
    int k = idx >> 9, j = idx & 511;
    float v = (j < 256) ? Wd[k * 256 + j] : Wg[k * 256 + (j - 256)];
    g_Wdg[idx] = __float2bfloat16(v);
}

__global__ void prep_bdg(const float* __restrict__ bd, const float* __restrict__ bg) {
    int j = threadIdx.x;  // 512 threads
    g_bdg[j] = (j < 256) ? bd[j] : bg[j - 256];
}

// Wvo = Wv @ Wo (fp32), 4 rows per CTA (grid 64): 4x load reuse + ILP.
__global__ void prep_wvo(const float* __restrict__ Wv, const float* __restrict__ Wo,
                         const float* __restrict__ bv, const float* __restrict__ bo) {
    __shared__ float rows[4][256];
    int j = threadIdx.x;
    int i0 = blockIdx.x * 4;
    #pragma unroll
    for (int r = 0; r < 4; r++) rows[r][j] = Wv[(i0 + r) * 256 + j];
    __syncthreads();
    float acc[4] = {0.f, 0.f, 0.f, 0.f};
    #pragma unroll 4
    for (int k = 0; k < 256; k++) {
        float wo = Wo[k * 256 + j];
        acc[0] += rows[0][k] * wo;
        acc[1] += rows[1][k] * wo;
        acc[2] += rows[2][k] * wo;
        acc[3] += rows[3][k] * wo;
    }
    #pragma unroll
    for (int r = 0; r < 4; r++) g_Wvof[(i0 + r) * 256 + j] = acc[r];
    if (blockIdx.x == 0) {
        float b0 = 0.f, b1_ = 0.f;
        for (int k = 0; k < 256; k += 2) {
            b0  += bv[k] * Wo[k * 256 + j];
            b1_ += bv[k + 1] * Wo[(k + 1) * 256 + j];
        }
        g_bvo[j] = b0 + b1_ + bo[j];
    }
}

// W23 = W2 @ Wvo (bf16 out), 4 rows per CTA.
__global__ void prep_w2vo(const float* __restrict__ W2, const float* __restrict__ b2) {
    __shared__ float rows[4][256];
    int j = threadIdx.x;
    int i0 = blockIdx.x * 4;
    #pragma unroll
    for (int r = 0; r < 4; r++) rows[r][j] = W2[(i0 + r) * 256 + j];
    __syncthreads();
    float acc[4] = {0.f, 0.f, 0.f, 0.f};
    #pragma unroll 4
    for (int k = 0; k < 256; k++) {
        float wv = g_Wvof[k * 256 + j];
        acc[0] += rows[0][k] * wv;
        acc[1] += rows[1][k] * wv;
        acc[2] += rows[2][k] * wv;
        acc[3] += rows[3][k] * wv;
    }
    #pragma unroll
    for (int r = 0; r < 4; r++) g_W23[(i0 + r) * 256 + j] = __float2bfloat16(acc[r]);
    if (blockIdx.x == 0) {
        float b0 = 0.f, b1_ = 0.f;
        for (int k = 0; k < 256; k += 2) {
            b0  += b2[k] * g_Wvof[k * 256 + j];
            b1_ += b2[k + 1] * g_Wvof[(k + 1) * 256 + j];
        }
        g_b23[j] = b0 + b1_ + g_bvo[j];
    }
}

__global__ void prep_T(const float* __restrict__ Wu, const float* __restrict__ Wld) {
    int i = blockIdx.x, t = threadIdx.x;
    int r = t & 15, seg = t >> 4;
    float acc = 0.f;
    int k0 = seg * 64;
    #pragma unroll 4
    for (int k = k0; k < k0 + 64; k++) acc += Wu[i * 1024 + k] * Wld[k * 16 + r];
    __shared__ float red[256];
    red[t] = acc;
    __syncthreads();
    if (seg == 0) {
        float s = 0.f;
        #pragma unroll
        for (int q = 0; q < 16; q++) s += red[q * 16 + r];
        g_T[i * 16 + r] = s;
    }
}

__global__ void prep_wu2(const float* __restrict__ Wu, const float* __restrict__ Wlu) {
    int i = blockIdx.x;
    int j = blockIdx.y * 256 + threadIdx.x;
    __shared__ float Ti[16];
    if (threadIdx.x < 16) Ti[threadIdx.x] = g_T[i * 16 + threadIdx.x];
    __syncthreads();
    float acc = Wu[i * 1024 + j];
    #pragma unroll
    for (int r = 0; r < 16; r++) acc += Ti[r] * Wlu[r * 1024 + j];
    g_Wu2[i * 1024 + j] = __float2bfloat16(acc);
}

__global__ void prep_bu2(const float* __restrict__ bu, const float* __restrict__ Wld,
                         const float* __restrict__ Wlu) {
    __shared__ float s[16];
    int t = threadIdx.x;
    if (t < 16) {
        float a = 0.f;
        for (int k = 0; k < 1024; k++) a += bu[k] * Wld[k * 16 + t];
        s[t] = a;
    }
    __syncthreads();
    float acc = bu[t];
    #pragma unroll
    for (int r = 0; r < 16; r++) acc += s[r] * Wlu[r * 1024 + t];
    g_bu2[t] = acc;
}

// ---------------- LayerNorm: one warp per row ----------------
__global__ void ln_kernel(const float* __restrict__ x, const float* __restrict__ gw,
                          const float* __restrict__ bw) {
    int warp = threadIdx.x >> 5, lane = threadIdx.x & 31;
    int row = blockIdx.x * 8 + warp;
    const float4* xr = (const float4*)(x + (size_t)row * CC);
    float4 v[8];
    float s = 0.f, q = 0.f;
    #pragma unroll
    for (int i = 0; i < 8; i++) {
        v[i] = xr[lane + 32 * i];
        s += v[i].x + v[i].y + v[i].z + v[i].w;
        q += v[i].x * v[i].x + v[i].y * v[i].y + v[i].z * v[i].z + v[i].w * v[i].w;
    }
    #pragma unroll
    for (int o = 16; o; o >>= 1) {
        s += __shfl_xor_sync(0xffffffffu, s, o);
        q += __shfl_xor_sync(0xffffffffu, q, o);
    }
    float mu = s * (1.0f / 1024.0f);
    float var = q * (1.0f / 1024.0f) - mu * mu;
    float rs = rsqrtf(var + 1e-5f);
    uint2* dst = (uint2*)(g_xn + (size_t)row * CC);
    const float4* g4 = (const float4*)gw;
    const float4* b4 = (const float4*)bw;
    #pragma unroll
    for (int i = 0; i < 8; i++) {
        int idx = lane + 32 * i;
        float4 gg = g4[idx], bb = b4[idx];
        float y0 = (v[i].x - mu) * rs * gg.x + bb.x;
        float y1 = (v[i].y - mu) * rs * gg.y + bb.y;
        float y2 = (v[i].z - mu) * rs * gg.z + bb.z;
        float y3 = (v[i].w - mu) * rs * gg.w + bb.w;
        __nv_bfloat162 lo = __floats2bfloat162_rn(y0, y1);
        __nv_bfloat162 hi = __floats2bfloat162_rn(y2, y3);
        uint2 u;
        u.x = *reinterpret_cast<unsigned*>(&lo);
        u.y = *reinterpret_cast<unsigned*>(&hi);
        dst[idx] = u;
    }
}

// ================= pipelined smem GEMM machinery (measured-fast configs only) ===
#define AS2 5120    // 128 * 40 bf16 per A stage
#define BS2 4352    // 32 * 136 bf16 per B stage
#define SMEM_BYTES 37888

// ---------------- gemm1 fused with GLU + depthwise affine ----------------------
__global__ void __launch_bounds__(512, 2)
gemm1s_glu_kernel(const float* __restrict__ dw_w, const float* __restrict__ dw_b) {
    __shared__ __align__(16) char sm[SMEM_BYTES];
    bf16* sA = reinterpret_cast<bf16*>(sm);
    bf16* sB = reinterpret_cast<bf16*>(sm + 2 * AS2 * 2);
    uint32_t sA_u = (uint32_t)__cvta_generic_to_shared(sA);
    uint32_t sB_u = (uint32_t)__cvta_generic_to_shared(sB);

    int tid = threadIdx.x;
    int warp = tid >> 5;
    int mw = warp >> 2, nw = warp & 3;
    int row0 = blockIdx.y * 128;
    int base = blockIdx.x * 64;                 // d-col base (g at 256+base)

    wmma::fragment<wmma::accumulator, 16, 16, 16, float> cd[2], cg[2];
    #pragma unroll
    for (int i = 0; i < 2; i++) { wmma::fill_fragment(cd[i], 0.0f); wmma::fill_fragment(cg[i], 0.0f); }

    int ar = tid >> 2, ac = (tid & 3) << 3;     // A: 128 x 32
    int br = tid >> 4, bc = (tid & 15) << 3;    // B: 32 x 128 virtual (d | g)
    int bcol = (bc < 64) ? (base + bc) : (256 + base + (bc - 64));

    auto load_tile = [&](int stage, int k0) {
        cp16(sA_u + (stage * AS2 + ar * 40 + ac) * 2,
             g_xn + (size_t)(row0 + ar) * 1024 + k0 + ac);
        cp16(sB_u + (stage * BS2 + br * 136 + bc) * 2,
             g_Wdg + (size_t)(k0 + br) * 512 + bcol);
        asm volatile("cp.async.commit_group;\n");
    };

    load_tile(0, 0);
    const int KT = 32;                          // K = 1024 / 32
    for (int kt = 0; kt < KT; kt++) {
        int cur = kt & 1;
        if (kt + 1 < KT) {
            load_tile(cur ^ 1, (kt + 1) * 32);
            asm volatile("cp.async.wait_group 1;\n");
        } else {
            asm volatile("cp.async.wait_group 0;\n");
        }
        __syncthreads();
        #pragma unroll
        for (int ks = 0; ks < 2; ks++) {
            wmma::fragment<wmma::matrix_a, 16, 16, 16, bf16, wmma::row_major> a0, a1;
            wmma::fragment<wmma::matrix_b, 16, 16, 16, bf16, wmma::row_major> bd_, bg_;
            const bf16* pa = sA + cur * AS2 + (mw * 32) * 40 + ks * 16;
            wmma::load_matrix_sync(a0, pa, 40);
            wmma::load_matrix_sync(a1, pa + 16 * 40, 40);
            const bf16* pb = sB + cur * BS2 + (ks * 16) * 136;
            wmma::load_matrix_sync(bd_, pb + nw * 16, 136);
            wmma::load_matrix_sync(bg_, pb + 64 + nw * 16, 136);
            wmma::mma_sync(cd[0], a0, bd_, cd[0]);
            wmma::mma_sync(cd[1], a1, bd_, cd[1]);
            wmma::mma_sync(cg[0], a0, bg_, cg[0]);
            wmma::mma_sync(cg[1], a1, bg_, cg[1]);
        }
        __syncthreads();
    }

    // CTA-wide coalesced epilogue: two row-strip passes
    float* sC = reinterpret_cast<float*>(sm);
    #pragma unroll
    for (int i = 0; i < 2; i++) {
        __syncthreads();
        wmma::store_matrix_sync(sC + (mw * 16) * 136 + nw * 16,      cd[i], 136, wmma::mem_row_major);
        wmma::store_matrix_sync(sC + (mw * 16) * 136 + 68 + nw * 16, cg[i], 136, wmma::mem_row_major);
        __syncthreads();
        #pragma unroll
        for (int e = tid; e < 64 * 16; e += 512) {
            int r = e >> 4;
            int c4 = (e & 15) << 2;
            int grow = row0 + (r >> 4) * 32 + i * 16 + (r & 15);
            int gcol = base + c4;
            float4 bd4 = *(const float4*)(g_bdg + gcol);
            float4 bg4 = *(const float4*)(g_bdg + 256 + gcol);
            float4 w4  = *(const float4*)(dw_w + gcol);
            float4 db4 = *(const float4*)(dw_b + gcol);
            float d0 = sC[r * 136 + c4 + 0] + bd4.x;
            float d1 = sC[r * 136 + c4 + 1] + bd4.y;
            float d2 = sC[r * 136 + c4 + 2] + bd4.z;
            float d3 = sC[r * 136 + c4 + 3] + bd4.w;
            float q0 = sC[r * 136 + 68 + c4 + 0] + bg4.x;
            float q1 = sC[r * 136 + 68 + c4 + 1] + bg4.y;
            float q2 = sC[r * 136 + 68 + c4 + 2] + bg4.z;
            float q3 = sC[r * 136 + 68 + c4 + 3] + bg4.w;
            float h0 = d0 * (1.0f / (1.0f + __expf(-q0))) * w4.x + db4.x;
            float h1 = d1 * (1.0f / (1.0f + __expf(-q1))) * w4.y + db4.y;
            float h2 = d2 * (1.0f / (1.0f + __expf(-q2))) * w4.z + db4.z;
            float h3 = d3 * (1.0f / (1.0f + __expf(-q3))) * w4.w + db4.w;
            __nv_bfloat162 lo = __floats2bfloat162_rn(h0, h1);
            __nv_bfloat162 hi = __floats2bfloat162_rn(h2, h3);
            uint2 u;
            u.x = *reinterpret_cast<unsigned*>(&lo);
            u.y = *reinterpret_cast<unsigned*>(&hi);
            *(uint2*)(g_h1 + (size_t)(grow) * 256 + gcol) = u;
        }
    }
}

// ---------------- pipelined gemm2 (proven clone; + occupancy 2) ----------------
__global__ void __launch_bounds__(512, 2)
gemm2s_kernel(const float* __restrict__ b1) {
    __shared__ __align__(16) char sm[SMEM_BYTES];
    bf16* sA = reinterpret_cast<bf16*>(sm);
    bf16* sB = reinterpret_cast<bf16*>(sm + 2 * AS2 * 2);
    uint32_t sA_u = (uint32_t)__cvta_generic_to_shared(sA);
    uint32_t sB_u = (uint32_t)__cvta_generic_to_shared(sB);

    int tid = threadIdx.x;
    int warp = tid >> 5;
    int mw = warp >> 2, nw = warp & 3;
    int row0 = blockIdx.y * 128;
    int col0 = blockIdx.x * 128;

    wmma::fragment<wmma::accumulator, 16, 16, 16, float> c[2][2];
    #pragma unroll
    for (int i = 0; i < 2; i++)
        #pragma unroll
        for (int j = 0; j < 2; j++) wmma::fill_fragment(c[i][j], 0.0f);

    int ar = tid >> 2, ac = (tid & 3) << 3;
    int br = tid >> 4, bc = (tid & 15) << 3;

    auto load_tile = [&](int stage, int k0) {
        cp16(sA_u + (stage * AS2 + ar * 40 + ac) * 2,
             g_h1 + (size_t)(row0 + ar) * 256 + k0 + ac);
        cp16(sB_u + (stage * BS2 + br * 136 + bc) * 2,
             g_W1b + (size_t)(k0 + br) * 256 + col0 + bc);
        asm volatile("cp.async.commit_group;\n");
    };

    load_tile(0, 0);
    const int KT = 8;
    for (int kt = 0; kt < KT; kt++) {
        int cur = kt & 1;
        if (kt + 1 < KT) {
            load_tile(cur ^ 1, (kt + 1) * 32);
            asm volatile("cp.async.wait_group 1;\n");
        } else {
            asm volatile("cp.async.wait_group 0;\n");
        }
        __syncthreads();
        #pragma unroll
        for (int ks = 0; ks < 2; ks++) {
            wmma::fragment<wmma::matrix_a, 16, 16, 16, bf16, wmma::row_major> a0, a1;
            wmma::fragment<wmma::matrix_b, 16, 16, 16, bf16, wmma::row_major> b0, b1f;
            const bf16* pa = sA + cur * AS2 + (mw * 32) * 40 + ks * 16;
            wmma::load_matrix_sync(a0, pa, 40);
            wmma::load_matrix_sync(a1, pa + 16 * 40, 40);
            const bf16* pb = sB + cur * BS2 + (ks * 16) * 136 + nw * 32;
            wmma::load_matrix_sync(b0, pb, 136);
            wmma::load_matrix_sync(b1f, pb + 16, 136);
            wmma::mma_sync(c[0][0], a0, b0, c[0][0]);
            wmma::mma_sync(c[0][1], a0, b1f, c[0][1]);
            wmma::mma_sync(c[1][0], a1, b0, c[1][0]);
            wmma::mma_sync(c[1][1], a1, b1f, c[1][1]);
        }
        __syncthreads();
    }

    float* sC = reinterpret_cast<float*>(sm);
    #pragma unroll
    for (int i = 0; i < 2; i++) {
        __syncthreads();
        wmma::store_matrix_sync(sC + (mw * 16) * 132 + nw * 32,      c[i][0], 132, wmma::mem_row_major);
        wmma::store_matrix_sync(sC + (mw * 16) * 132 + nw * 32 + 16, c[i][1], 132, wmma::mem_row_major);
        __syncthreads();
        #pragma unroll
        for (int e = tid; e < 64 * 32; e += 512) {
            int r = e >> 5;
            int c4 = (e & 31) << 2;
            int grow = row0 + (r >> 4) * 32 + i * 16 + (r & 15);
            int gcol = col0 + c4;
            float4 bv = *(const float4*)(b1 + gcol);
            float v0 = gelu_tanh(sC[r * 132 + c4 + 0] + bv.x);
            float v1 = gelu_tanh(sC[r * 132 + c4 + 1] + bv.y);
            float v2 = gelu_tanh(sC[r * 132 + c4 + 2] + bv.z);
            float v3 = gelu_tanh(sC[r * 132 + c4 + 3] + bv.w);
            __nv_bfloat162 lo = __floats2bfloat162_rn(v0, v1);
            __nv_bfloat162 hi = __floats2bfloat162_rn(v2, v3);
            uint2 u;
            u.x = *reinterpret_cast<unsigned*>(&lo);
            u.y = *reinterpret_cast<unsigned*>(&hi);
            *(uint2*)(g_t + (size_t)grow * 256 + gcol) = u;
        }
    }
}

// ---------------- pipelined gemm3 (literal clone of gemm2s, no gelu) -----------
__global__ void __launch_bounds__(512, 2)
gemm3p_kernel() {
    __shared__ __align__(16) char sm[SMEM_BYTES];
    bf16* sA = reinterpret_cast<bf16*>(sm);
    bf16* sB = reinterpret_cast<bf16*>(sm + 2 * AS2 * 2);
    uint32_t sA_u = (uint32_t)__cvta_generic_to_shared(sA);
    uint32_t sB_u = (uint32_t)__cvta_generic_to_shared(sB);

    int tid = threadIdx.x;
    int warp = tid >> 5;
    int mw = warp >> 2, nw = warp & 3;
    int row0 = blockIdx.y * 128;
    int col0 = blockIdx.x * 128;

    wmma::fragment<wmma::accumulator, 16, 16, 16, float> c[2][2];
    #pragma unroll
    for (int i = 0; i < 2; i++)
        #pragma unroll
        for (int j = 0; j < 2; j++) wmma::fill_fragment(c[i][j], 0.0f);

    int ar = tid >> 2, ac = (tid & 3) << 3;
    int br = tid >> 4, bc = (tid & 15) << 3;

    auto load_tile = [&](int stage, int k0) {
        cp16(sA_u + (stage * AS2 + ar * 40 + ac) * 2,
             g_t + (size_t)(row0 + ar) * 256 + k0 + ac);
        cp16(sB_u + (stage * BS2 + br * 136 + bc) * 2,
             g_W23 + (size_t)(k0 + br) * 256 + col0 + bc);
        asm volatile("cp.async.commit_group;\n");
    };

    load_tile(0, 0);
    const int KT = 8;
    for (int kt = 0; kt < KT; kt++) {
        int cur = kt & 1;
        if (kt + 1 < KT) {
            load_tile(cur ^ 1, (kt + 1) * 32);
            asm volatile("cp.async.wait_group 1;\n");
        } else {
            asm volatile("cp.async.wait_group 0;\n");
        }
        __syncthreads();
        #pragma unroll
        for (int ks = 0; ks < 2; ks++) {
            wmma::fragment<wmma::matrix_a, 16, 16, 16, bf16, wmma::row_major> a0, a1;
            wmma::fragment<wmma::matrix_b, 16, 16, 16, bf16, wmma::row_major> b0, b1f;
            const bf16* pa = sA + cur * AS2 + (mw * 32) * 40 + ks * 16;
            wmma::load_matrix_sync(a0, pa, 40);
            wmma::load_matrix_sync(a1, pa + 16 * 40, 40);
            const bf16* pb = sB + cur * BS2 + (ks * 16) * 136 + nw * 32;
            wmma::load_matrix_sync(b0, pb, 136);
            wmma::load_matrix_sync(b1f, pb + 16, 136);
            wmma::mma_sync(c[0][0], a0, b0, c[0][0]);
            wmma::mma_sync(c[0][1], a0, b1f, c[0][1]);
            wmma::mma_sync(c[1][0], a1, b0, c[1][0]);
            wmma::mma_sync(c[1][1], a1, b1f, c[1][1]);
        }
        __syncthreads();
    }

    float* sC = reinterpret_cast<float*>(sm);
    #pragma unroll
    for (int i = 0; i < 2; i++) {
        __syncthreads();
        wmma::store_matrix_sync(sC + (mw * 16) * 132 + nw * 32,      c[i][0], 132, wmma::mem_row_major);
        wmma::store_matrix_sync(sC + (mw * 16) * 132 + nw * 32 + 16, c[i][1], 132, wmma::mem_row_major);
        __syncthreads();
        #pragma unroll
        for (int e = tid; e < 64 * 32; e += 512) {
            int r = e >> 5;
            int c4 = (e & 31) << 2;
            int grow = row0 + (r >> 4) * 32 + i * 16 + (r & 15);
            int gcol = col0 + c4;
            float4 bv = *(const float4*)(g_b23 + gcol);
            float v0 = sC[r * 132 + c4 + 0] + bv.x;
            float v1 = sC[r * 132 + c4 + 1] + bv.y;
            float v2 = sC[r * 132 + c4 + 2] + bv.z;
            float v3 = sC[r * 132 + c4 + 3] + bv.w;
            __nv_bfloat162 lo = __floats2bfloat162_rn(v0, v1);
            __nv_bfloat162 hi = __floats2bfloat162_rn(v2, v3);
            uint2 u;
            u.x = *reinterpret_cast<unsigned*>(&lo);
            u.y = *reinterpret_cast<unsigned*>(&hi);
            *(uint2*)(g_h3 + (size_t)grow * 256 + gcol) = u;
        }
    }
}

// ---------------- direct-WMMA gemm5 (proven), 64x128 block tile ----------------
__global__ void gemm5_kernel(float* __restrict__ out, const float* __restrict__ x) {
    const int N = 1024, K = 256;
    __shared__ float sC[64 * 132];
    int warp = threadIdx.x >> 5;
    int mw = warp >> 2, nw = warp & 3;
    int row0 = blockIdx.y * 64 + mw * 32;
    int col0 = blockIdx.x * 128 + nw * 32;

    wmma::fragment<wmma::accumulator, 16, 16, 16, float> c[2][2];
    #pragma unroll
    for (int i = 0; i < 2; i++)
        #pragma unroll
        for (int j = 0; j < 2; j++) wmma::fill_fragment(c[i][j], 0.0f);

    const bf16* Aptr = g_h3 + (size_t)row0 * K;
    #pragma unroll 4
    for (int k = 0; k < K; k += 16) {
        wmma::fragment<wmma::matrix_a, 16, 16, 16, bf16, wmma::row_major> a0, a1;
        wmma::fragment<wmma::matrix_b, 16, 16, 16, bf16, wmma::row_major> b0, b1;
        wmma::load_matrix_sync(a0, Aptr + k, K);
        wmma::load_matrix_sync(a1, Aptr + (size_t)16 * K + k, K);
        wmma::load_matrix_sync(b0, g_Wu2 + (size_t)k * N + col0, N);
        wmma::load_matrix_sync(b1, g_Wu2 + (size_t)k * N + col0 + 16, N);
        wmma::mma_sync(c[0][0], a0, b0, c[0][0]);
        wmma::mma_sync(c[0][1], a0, b1, c[0][1]);
        wmma::mma_sync(c[1][0], a1, b0, c[1][0]);
        wmma::mma_sync(c[1][1], a1, b1, c[1][1]);
    }

    #pragma unroll
    for (int i = 0; i < 2; i++)
        #pragma unroll
        for (int j = 0; j < 2; j++)
            wmma::store_matrix_sync(sC + (mw * 32 + 16 * i) * 132 + nw * 32 + 16 * j,
                                    c[i][j], 132, wmma::mem_row_major);
    __syncthreads();

    #pragma unroll
    for (int e = threadIdx.x; e < 64 * 32; e += 256) {
        int r = e >> 5;
        int c4 = (e & 31) << 2;
        int grow = blockIdx.y * 64 + r;
        int gcol = blockIdx.x * 128 + c4;
        float4 bv = *(const float4*)(g_bu2 + gcol);
        float v0 = sC[r * 132 + c4 + 0] + bv.x;
        float v1 = sC[r * 132 + c4 + 1] + bv.y;
        float v2 = sC[r * 132 + c4 + 2] + bv.z;
        float v3 = sC[r * 132 + c4 + 3] + bv.w;
        float4 xv = *(const float4*)(x + (size_t)grow * N + gcol);
        float4 o;
        o.x = 0.5f * v0 + 0.5f * xv.x;
        o.y = 0.5f * v1 + 0.5f * xv.y;
        o.z = 0.5f * v2 + 0.5f * xv.z;
        o.w = 0.5f * v3 + 0.5f * xv.w;
        *(float4*)(out + (size_t)grow * N + gcol) = o;
    }
}

// ---------------- launcher ----------------
extern "C" void kernel_launch(void* const* d_in, const int* in_sizes, int n_in,
                              void* d_out, int out_size) {
    const float* x    = (const float*)d_in[0];
    const float* ln_g = (const float*)d_in[1];
    const float* ln_b = (const float*)d_in[2];
    const float* Wd   = (const float*)d_in[3];
    const float* bd   = (const float*)d_in[4];
    const float* Wg   = (const float*)d_in[5];
    const float* bg   = (const float*)d_in[6];
    const float* dw_w = (const float*)d_in[7];
    const float* dw_b = (const float*)d_in[8];
    const float* W1   = (const float*)d_in[9];
    const float* b1   = (const float*)d_in[10];
    const float* W2   = (const float*)d_in[11];
    const float* b2   = (const float*)d_in[12];
    // d_in[13..16] = Wq,bq,Wk,bk : dead (softmax over a single key == 1)
    const float* Wv   = (const float*)d_in[17];
    const float* bv   = (const float*)d_in[18];
    const float* Wo   = (const float*)d_in[19];
    const float* bo   = (const float*)d_in[20];
    const float* Wu   = (const float*)d_in[21];
    const float* bu   = (const float*)d_in[22];
    const float* Wld  = (const float*)d_in[23];
    const float* Wlu  = (const float*)d_in[24];
    float* out = (float*)d_out;

    prep_wdg<<<(1024 * 512) / 256, 256>>>(Wd, Wg);                    // 1
    prep_bdg<<<1, 512>>>(bd, bg);                                     // 2
    ln_kernel<<<BB / 8, 256>>>(x, ln_g, ln_b);                        // 3
    gemm1s_glu_kernel<<<dim3(4, BB / 128), 512>>>(dw_w, dw_b);        // 4 (ncu slot)
    cvt_kernel<<<(256 * 256 + 255) / 256, 256>>>(W1, g_W1b, 256*256); // 5
    gemm2s_kernel<<<dim3(2, BB / 128), 512>>>(b1);                    // 6
    prep_wvo<<<64, 256>>>(Wv, Wo, bv, bo);                            // 7
    prep_w2vo<<<64, 256>>>(W2, b2);                                   // 8
    gemm3p_kernel<<<dim3(2, BB / 128), 512>>>();                      // 9
    prep_T<<<256, 256>>>(Wu, Wld);                                    // 10
    prep_wu2<<<dim3(256, 4), 256>>>(Wu, Wlu);                         // 11
    prep_bu2<<<1, 1024>>>(bu, Wld, Wlu);                              // 12
    gemm5_kernel<<<dim3(8, BB / 64), 256>>>(out, x);                  // 13 (direct, proven)
}

// round 14
// speedup vs baseline: 8.8451x; 1.3228x over previous
#include <cuda_runtime.h>
#include <cuda_bf16.h>
#include <mma.h>
#include <cstdint>

using namespace nvcuda;

#define BB 32768
#define CC 1024
#define CH 256

typedef __nv_bfloat16 bf16;

// ---------------- device scratch (static, no allocation) ----------------
__device__ __align__(16) bf16  g_xn[(size_t)BB * CC];        // LN output, bf16
__device__ __align__(16) bf16  g_h1[(size_t)BB * CH];
__device__ __align__(16) bf16  g_t [(size_t)BB * CH];
__device__ __align__(16) bf16  g_h3[(size_t)BB * CH];

__device__ __align__(16) bf16  g_Wdg[1024 * 512];            // [Wd | Wg] bf16
__device__ __align__(16) float g_bdg[512];
__device__ __align__(16) bf16  g_W1b[256 * 256];
__device__ __align__(16) float g_Wvof[256 * 256];            // fp32 Wv@Wo
__device__ __align__(16) float g_bvo[256];
__device__ __align__(16) bf16  g_W23[256 * 256];             // W2 @ (Wv@Wo)
__device__ __align__(16) float g_b23[256];
__device__ __align__(16) bf16  g_Wu2[256 * 1024];            // Wu + (Wu@Wld)@Wlu
__device__ __align__(16) float g_bu2[1024];
__device__ __align__(16) float g_T[256 * 16];

// ---------------- helpers ----------------
__device__ __forceinline__ float gelu_tanh(float x) {
    float x3 = x * x * x;
    return 0.5f * x * (1.0f + tanhf(0.7978845608028654f * (x + 0.044715f * x3)));
}

__device__ __forceinline__ void cp16(uint32_t d, const void* s) {
    asm volatile("cp.async.cg.shared.global [%0], [%1], 16;\n" :: "r"(d), "l"(s));
}

// ---------------- prep kernels ----------------
__global__ void cvt_kernel(const float* __restrict__ src, bf16* __restrict__ dst, int n) {
    int i = blockIdx.x * 256 + threadIdx.x;
    if (i < n) dst[i] = __float2bfloat16(src[i]);
}

__global__ void prep_wdg(const float* __restrict__ Wd, const float* __restrict__ Wg) {
    int idx = blockIdx.x * 256 + threadIdx.x;   // < 1024*512
    int k = idx >> 9, j = idx & 511;
    float v = (j < 256) ? Wd[k * 256 + j] : Wg[k * 256 + (j - 256)];
    g_Wdg[idx] = __float2bfloat16(v);
}

__global__ void prep_bdg(const float* __restrict__ bd, const float* __restrict__ bg) {
    int j = threadIdx.x;  // 512 threads
    g_bdg[j] = (j < 256) ? bd[j] : bg[j - 256];
}

// Wvo = Wv @ Wo (fp32), 4 rows per CTA (grid 64): 4x load reuse + ILP.
__global__ void prep_wvo(const float* __restrict__ Wv, const float* __restrict__ Wo,
                         const float* __restrict__ bv, const float* __restrict__ bo) {
    __shared__ float rows[4][256];
    int j = threadIdx.x;
    int i0 = blockIdx.x * 4;
    #pragma unroll
    for (int r = 0; r < 4; r++) rows[r][j] = Wv[(i0 + r) * 256 + j];
    __syncthreads();
    float acc[4] = {0.f, 0.f, 0.f, 0.f};
    #pragma unroll 4
    for (int k = 0; k < 256; k++) {
        float wo = Wo[k * 256 + j];
        acc[0] += rows[0][k] * wo;
        acc[1] += rows[1][k] * wo;
        acc[2] += rows[2][k] * wo;
        acc[3] += rows[3][k] * wo;
    }
    #pragma unroll
    for (int r = 0; r < 4; r++) g_Wvof[(i0 + r) * 256 + j] = acc[r];
    if (blockIdx.x == 0) {
        float b0 = 0.f, b1_ = 0.f;
        for (int k = 0; k < 256; k += 2) {
            b0  += bv[k] * Wo[k * 256 + j];
            b1_ += bv[k + 1] * Wo[(k + 1) * 256 + j];
        }
        g_bvo[j] = b0 + b1_ + bo[j];
    }
}

// W23 = W2 @ Wvo (bf16 out), 4 rows per CTA.
__global__ void prep_w2vo(const float* __restrict__ W2, const float* __restrict__ b2) {
    __shared__ float rows[4][256];
    int j = threadIdx.x;
    int i0 = blockIdx.x * 4;
    #pragma unroll
    for (int r = 0; r < 4; r++) rows[r][j] = W2[(i0 + r) * 256 + j];
    __syncthreads();
    float acc[4] = {0.f, 0.f, 0.f, 0.f};
    #pragma unroll 4
    for (int k = 0; k < 256; k++) {
        float wv = g_Wvof[k * 256 + j];
        acc[0] += rows[0][k] * wv;
        acc[1] += rows[1][k] * wv;
        acc[2] += rows[2][k] * wv;
        acc[3] += rows[3][k] * wv;
    }
    #pragma unroll
    for (int r = 0; r < 4; r++) g_W23[(i0 + r) * 256 + j] = __float2bfloat16(acc[r]);
    if (blockIdx.x == 0) {
        float b0 = 0.f, b1_ = 0.f;
        for (int k = 0; k < 256; k += 2) {
            b0  += b2[k] * g_Wvof[k * 256 + j];
            b1_ += b2[k + 1] * g_Wvof[(k + 1) * 256 + j];
        }
        g_b23[j] = b0 + b1_ + g_bvo[j];
    }
}

__global__ void prep_T(const float* __restrict__ Wu, const float* __restrict__ Wld) {
    int i = blockIdx.x, t = threadIdx.x;
    int r = t & 15, seg = t >> 4;
    float acc = 0.f;
    int k0 = seg * 64;
    #pragma unroll 4
    for (int k = k0; k < k0 + 64; k++) acc += Wu[i * 1024 + k] * Wld[k * 16 + r];
    __shared__ float red[256];
    red[t] = acc;
    __syncthreads();
    if (seg == 0) {
        float s = 0.f;
        #pragma unroll
        for (int q = 0; q < 16; q++) s += red[q * 16 + r];
        g_T[i * 16 + r] = s;
    }
}

__global__ void prep_wu2(const float* __restrict__ Wu, const float* __restrict__ Wlu) {
    int i = blockIdx.x;
    int j = blockIdx.y * 256 + threadIdx.x;
    __shared__ float Ti[16];
    if (threadIdx.x < 16) Ti[threadIdx.x] = g_T[i * 16 + threadIdx.x];
    __syncthreads();
    float acc = Wu[i * 1024 + j];
    #pragma unroll
    for (int r = 0; r < 16; r++) acc += Ti[r] * Wlu[r * 1024 + j];
    g_Wu2[i * 1024 + j] = __float2bfloat16(acc);
}

__global__ void prep_bu2(const float* __restrict__ bu, const float* __restrict__ Wld,
                         const float* __restrict__ Wlu) {
    __shared__ float s[16];
    int t = threadIdx.x;
    if (t < 16) {
        float a = 0.f;
        for (int k = 0; k < 1024; k++) a += bu[k] * Wld[k * 16 + t];
        s[t] = a;
    }
    __syncthreads();
    float acc = bu[t];
    #pragma unroll
    for (int r = 0; r < 16; r++) acc += s[r] * Wlu[r * 1024 + t];
    g_bu2[t] = acc;
}

// ---------------- LayerNorm: one warp per row ----------------
__global__ void ln_kernel(const float* __restrict__ x, const float* __restrict__ gw,
                          const float* __restrict__ bw) {
    int warp = threadIdx.x >> 5, lane = threadIdx.x & 31;
    int row = blockIdx.x * 8 + warp;
    const float4* xr = (const float4*)(x + (size_t)row * CC);
    float4 v[8];
    float s = 0.f, q = 0.f;
    #pragma unroll
    for (int i = 0; i < 8; i++) {
        v[i] = xr[lane + 32 * i];
        s += v[i].x + v[i].y + v[i].z + v[i].w;
        q += v[i].x * v[i].x + v[i].y * v[i].y + v[i].z * v[i].z + v[i].w * v[i].w;
    }
    #pragma unroll
    for (int o = 16; o; o >>= 1) {
        s += __shfl_xor_sync(0xffffffffu, s, o);
        q += __shfl_xor_sync(0xffffffffu, q, o);
    }
    float mu = s * (1.0f / 1024.0f);
    float var = q * (1.0f / 1024.0f) - mu * mu;
    float rs = rsqrtf(var + 1e-5f);
    uint2* dst = (uint2*)(g_xn + (size_t)row * CC);
    const float4* g4 = (const float4*)gw;
    const float4* b4 = (const float4*)bw;
    #pragma unroll
    for (int i = 0; i < 8; i++) {
        int idx = lane + 32 * i;
        float4 gg = g4[idx], bb = b4[idx];
        float y0 = (v[i].x - mu) * rs * gg.x + bb.x;
        float y1 = (v[i].y - mu) * rs * gg.y + bb.y;
        float y2 = (v[i].z - mu) * rs * gg.z + bb.z;
        float y3 = (v[i].w - mu) * rs * gg.w + bb.w;
        __nv_bfloat162 lo = __floats2bfloat162_rn(y0, y1);
        __nv_bfloat162 hi = __floats2bfloat162_rn(y2, y3);
        uint2 u;
        u.x = *reinterpret_cast<unsigned*>(&lo);
        u.y = *reinterpret_cast<unsigned*>(&hi);
        dst[idx] = u;
    }
}

// ================= pipelined smem GEMM machinery (measured-fast configs only) ===
#define AS2 5120    // 128 * 40 bf16 per A stage
#define BS2 4352    // 32 * 136 bf16 per B stage
#define SMEM_BYTES 37888

// ---------------- gemm1 fused with GLU + depthwise affine ----------------------
__global__ void __launch_bounds__(512, 2)
gemm1s_glu_kernel(const float* __restrict__ dw_w, const float* __restrict__ dw_b) {
    __shared__ __align__(16) char sm[SMEM_BYTES];
    bf16* sA = reinterpret_cast<bf16*>(sm);
    bf16* sB = reinterpret_cast<bf16*>(sm + 2 * AS2 * 2);
    uint32_t sA_u = (uint32_t)__cvta_generic_to_shared(sA);
    uint32_t sB_u = (uint32_t)__cvta_generic_to_shared(sB);

    int tid = threadIdx.x;
    int warp = tid >> 5;
    int mw = warp >> 2, nw = warp & 3;
    int row0 = blockIdx.y * 128;
    int base = blockIdx.x * 64;                 // d-col base (g at 256+base)

    wmma::fragment<wmma::accumulator, 16, 16, 16, float> cd[2], cg[2];
    #pragma unroll
    for (int i = 0; i < 2; i++) { wmma::fill_fragment(cd[i], 0.0f); wmma::fill_fragment(cg[i], 0.0f); }

    int ar = tid >> 2, ac = (tid & 3) << 3;     // A: 128 x 32
    int br = tid >> 4, bc = (tid & 15) << 3;    // B: 32 x 128 virtual (d | g)
    int bcol = (bc < 64) ? (base + bc) : (256 + base + (bc - 64));

    auto load_tile = [&](int stage, int k0) {
        cp16(sA_u + (stage * AS2 + ar * 40 + ac) * 2,
             g_xn + (size_t)(row0 + ar) * 1024 + k0 + ac);
        cp16(sB_u + (stage * BS2 + br * 136 + bc) * 2,
             g_Wdg + (size_t)(k0 + br) * 512 + bcol);
        asm volatile("cp.async.commit_group;\n");
    };

    load_tile(0, 0);
    const int KT = 32;                          // K = 1024 / 32
    for (int kt = 0; kt < KT; kt++) {
        int cur = kt & 1;
        if (kt + 1 < KT) {
            load_tile(cur ^ 1, (kt + 1) * 32);
            asm volatile("cp.async.wait_group 1;\n");
        } else {
            asm volatile("cp.async.wait_group 0;\n");
        }
        __syncthreads();
        #pragma unroll
        for (int ks = 0; ks < 2; ks++) {
            wmma::fragment<wmma::matrix_a, 16, 16, 16, bf16, wmma::row_major> a0, a1;
            wmma::fragment<wmma::matrix_b, 16, 16, 16, bf16, wmma::row_major> bd_, bg_;
            const bf16* pa = sA + cur * AS2 + (mw * 32) * 40 + ks * 16;
            wmma::load_matrix_sync(a0, pa, 40);
            wmma::load_matrix_sync(a1, pa + 16 * 40, 40);
            const bf16* pb = sB + cur * BS2 + (ks * 16) * 136;
            wmma::load_matrix_sync(bd_, pb + nw * 16, 136);
            wmma::load_matrix_sync(bg_, pb + 64 + nw * 16, 136);
            wmma::mma_sync(cd[0], a0, bd_, cd[0]);
            wmma::mma_sync(cd[1], a1, bd_, cd[1]);
            wmma::mma_sync(cg[0], a0, bg_, cg[0]);
            wmma::mma_sync(cg[1], a1, bg_, cg[1]);
        }
        __syncthreads();
    }

    // CTA-wide coalesced epilogue: two row-strip passes
    float* sC = reinterpret_cast<float*>(sm);
    #pragma unroll
    for (int i = 0; i < 2; i++) {
        __syncthreads();
        wmma::store_matrix_sync(sC + (mw * 16) * 136 + nw * 16,      cd[i], 136, wmma::mem_row_major);
        wmma::store_matrix_sync(sC + (mw * 16) * 136 + 68 + nw * 16, cg[i], 136, wmma::mem_row_major);
        __syncthreads();
        #pragma unroll
        for (int e = tid; e < 64 * 16; e += 512) {
            int r = e >> 4;
            int c4 = (e & 15) << 2;
            int grow = row0 + (r >> 4) * 32 + i * 16 + (r & 15);
            int gcol = base + c4;
            float4 bd4 = *(const float4*)(g_bdg + gcol);
            float4 bg4 = *(const float4*)(g_bdg + 256 + gcol);
            float4 w4  = *(const float4*)(dw_w + gcol);
            float4 db4 = *(const float4*)(dw_b + gcol);
            float d0 = sC[r * 136 + c4 + 0] + bd4.x;
            float d1 = sC[r * 136 + c4 + 1] + bd4.y;
            float d2 = sC[r * 136 + c4 + 2] + bd4.z;
            float d3 = sC[r * 136 + c4 + 3] + bd4.w;
            float q0 = sC[r * 136 + 68 + c4 + 0] + bg4.x;
            float q1 = sC[r * 136 + 68 + c4 + 1] + bg4.y;
            float q2 = sC[r * 136 + 68 + c4 + 2] + bg4.z;
            float q3 = sC[r * 136 + 68 + c4 + 3] + bg4.w;
            float h0 = d0 * (1.0f / (1.0f + __expf(-q0))) * w4.x + db4.x;
            float h1 = d1 * (1.0f / (1.0f + __expf(-q1))) * w4.y + db4.y;
            float h2 = d2 * (1.0f / (1.0f + __expf(-q2))) * w4.z + db4.z;
            float h3 = d3 * (1.0f / (1.0f + __expf(-q3))) * w4.w + db4.w;
            __nv_bfloat162 lo = __floats2bfloat162_rn(h0, h1);
            __nv_bfloat162 hi = __floats2bfloat162_rn(h2, h3);
            uint2 u;
            u.x = *reinterpret_cast<unsigned*>(&lo);
            u.y = *reinterpret_cast<unsigned*>(&hi);
            *(uint2*)(g_h1 + (size_t)(grow) * 256 + gcol) = u;
        }
    }
}

// ---------------- pipelined gemm2 (proven clone) -------------------------------
__global__ void __launch_bounds__(512, 2)
gemm2s_kernel(const float* __restrict__ b1) {
    __shared__ __align__(16) char sm[SMEM_BYTES];
    bf16* sA = reinterpret_cast<bf16*>(sm);
    bf16* sB = reinterpret_cast<bf16*>(sm + 2 * AS2 * 2);
    uint32_t sA_u = (uint32_t)__cvta_generic_to_shared(sA);
    uint32_t sB_u = (uint32_t)__cvta_generic_to_shared(sB);

    int tid = threadIdx.x;
    int warp = tid >> 5;
    int mw = warp >> 2, nw = warp & 3;
    int row0 = blockIdx.y * 128;
    int col0 = blockIdx.x * 128;

    wmma::fragment<wmma::accumulator, 16, 16, 16, float> c[2][2];
    #pragma unroll
    for (int i = 0; i < 2; i++)
        #pragma unroll
        for (int j = 0; j < 2; j++) wmma::fill_fragment(c[i][j], 0.0f);

    int ar = tid >> 2, ac = (tid & 3) << 3;
    int br = tid >> 4, bc = (tid & 15) << 3;

    auto load_tile = [&](int stage, int k0) {
        cp16(sA_u + (stage * AS2 + ar * 40 + ac) * 2,
             g_h1 + (size_t)(row0 + ar) * 256 + k0 + ac);
        cp16(sB_u + (stage * BS2 + br * 136 + bc) * 2,
             g_W1b + (size_t)(k0 + br) * 256 + col0 + bc);
        asm volatile("cp.async.commit_group;\n");
    };

    load_tile(0, 0);
    const int KT = 8;
    for (int kt = 0; kt < KT; kt++) {
        int cur = kt & 1;
        if (kt + 1 < KT) {
            load_tile(cur ^ 1, (kt + 1) * 32);
            asm volatile("cp.async.wait_group 1;\n");
        } else {
            asm volatile("cp.async.wait_group 0;\n");
        }
        __syncthreads();
        #pragma unroll
        for (int ks = 0; ks < 2; ks++) {
            wmma::fragment<wmma::matrix_a, 16, 16, 16, bf16, wmma::row_major> a0, a1;
            wmma::fragment<wmma::matrix_b, 16, 16, 16, bf16, wmma::row_major> b0, b1f;
            const bf16* pa = sA + cur * AS2 + (mw * 32) * 40 + ks * 16;
            wmma::load_matrix_sync(a0, pa, 40);
            wmma::load_matrix_sync(a1, pa + 16 * 40, 40);
            const bf16* pb = sB + cur * BS2 + (ks * 16) * 136 + nw * 32;
            wmma::load_matrix_sync(b0, pb, 136);
            wmma::load_matrix_sync(b1f, pb + 16, 136);
            wmma::mma_sync(c[0][0], a0, b0, c[0][0]);
            wmma::mma_sync(c[0][1], a0, b1f, c[0][1]);
            wmma::mma_sync(c[1][0], a1, b0, c[1][0]);
            wmma::mma_sync(c[1][1], a1, b1f, c[1][1]);
        }
        __syncthreads();
    }

    float* sC = reinterpret_cast<float*>(sm);
    #pragma unroll
    for (int i = 0; i < 2; i++) {
        __syncthreads();
        wmma::store_matrix_sync(sC + (mw * 16) * 132 + nw * 32,      c[i][0], 132, wmma::mem_row_major);
        wmma::store_matrix_sync(sC + (mw * 16) * 132 + nw * 32 + 16, c[i][1], 132, wmma::mem_row_major);
        __syncthreads();
        #pragma unroll
        for (int e = tid; e < 64 * 32; e += 512) {
            int r = e >> 5;
            int c4 = (e & 31) << 2;
            int grow = row0 + (r >> 4) * 32 + i * 16 + (r & 15);
            int gcol = col0 + c4;
            float4 bv = *(const float4*)(b1 + gcol);
            float v0 = gelu_tanh(sC[r * 132 + c4 + 0] + bv.x);
            float v1 = gelu_tanh(sC[r * 132 + c4 + 1] + bv.y);
            float v2 = gelu_tanh(sC[r * 132 + c4 + 2] + bv.z);
            float v3 = gelu_tanh(sC[r * 132 + c4 + 3] + bv.w);
            __nv_bfloat162 lo = __floats2bfloat162_rn(v0, v1);
            __nv_bfloat162 hi = __floats2bfloat162_rn(v2, v3);
            uint2 u;
            u.x = *reinterpret_cast<unsigned*>(&lo);
            u.y = *reinterpret_cast<unsigned*>(&hi);
            *(uint2*)(g_t + (size_t)grow * 256 + gcol) = u;
        }
    }
}

// ---------------- pipelined gemm3 (literal clone, no gelu) ---------------------
__global__ void __launch_bounds__(512, 2)
gemm3p_kernel() {
    __shared__ __align__(16) char sm[SMEM_BYTES];
    bf16* sA = reinterpret_cast<bf16*>(sm);
    bf16* sB = reinterpret_cast<bf16*>(sm + 2 * AS2 * 2);
    uint32_t sA_u = (uint32_t)__cvta_generic_to_shared(sA);
    uint32_t sB_u = (uint32_t)__cvta_generic_to_shared(sB);

    int tid = threadIdx.x;
    int warp = tid >> 5;
    int mw = warp >> 2, nw = warp & 3;
    int row0 = blockIdx.y * 128;
    int col0 = blockIdx.x * 128;

    wmma::fragment<wmma::accumulator, 16, 16, 16, float> c[2][2];
    #pragma unroll
    for (int i = 0; i < 2; i++)
        #pragma unroll
        for (int j = 0; j < 2; j++) wmma::fill_fragment(c[i][j], 0.0f);

    int ar = tid >> 2, ac = (tid & 3) << 3;
    int br = tid >> 4, bc = (tid & 15) << 3;

    auto load_tile = [&](int stage, int k0) {
        cp16(sA_u + (stage * AS2 + ar * 40 + ac) * 2,
             g_t + (size_t)(row0 + ar) * 256 + k0 + ac);
        cp16(sB_u + (stage * BS2 + br * 136 + bc) * 2,
             g_W23 + (size_t)(k0 + br) * 256 + col0 + bc);
        asm volatile("cp.async.commit_group;\n");
    };

    load_tile(0, 0);
    const int KT = 8;
    for (int kt = 0; kt < KT; kt++) {
        int cur = kt & 1;
        if (kt + 1 < KT) {
            load_tile(cur ^ 1, (kt + 1) * 32);
            asm volatile("cp.async.wait_group 1;\n");
        } else {
            asm volatile("cp.async.wait_group 0;\n");
        }
        __syncthreads();
        #pragma unroll
        for (int ks = 0; ks < 2; ks++) {
            wmma::fragment<wmma::matrix_a, 16, 16, 16, bf16, wmma::row_major> a0, a1;
            wmma::fragment<wmma::matrix_b, 16, 16, 16, bf16, wmma::row_major> b0, b1f;
            const bf16* pa = sA + cur * AS2 + (mw * 32) * 40 + ks * 16;
            wmma::load_matrix_sync(a0, pa, 40);
            wmma::load_matrix_sync(a1, pa + 16 * 40, 40);
            const bf16* pb = sB + cur * BS2 + (ks * 16) * 136 + nw * 32;
            wmma::load_matrix_sync(b0, pb, 136);
            wmma::load_matrix_sync(b1f, pb + 16, 136);
            wmma::mma_sync(c[0][0], a0, b0, c[0][0]);
            wmma::mma_sync(c[0][1], a0, b1f, c[0][1]);
            wmma::mma_sync(c[1][0], a1, b0, c[1][0]);
            wmma::mma_sync(c[1][1], a1, b1f, c[1][1]);
        }
        __syncthreads();
    }

    float* sC = reinterpret_cast<float*>(sm);
    #pragma unroll
    for (int i = 0; i < 2; i++) {
        __syncthreads();
        wmma::store_matrix_sync(sC + (mw * 16) * 132 + nw * 32,      c[i][0], 132, wmma::mem_row_major);
        wmma::store_matrix_sync(sC + (mw * 16) * 132 + nw * 32 + 16, c[i][1], 132, wmma::mem_row_major);
        __syncthreads();
        #pragma unroll
        for (int e = tid; e < 64 * 32; e += 512) {
            int r = e >> 5;
            int c4 = (e & 31) << 2;
            int grow = row0 + (r >> 4) * 32 + i * 16 + (r & 15);
            int gcol = col0 + c4;
            float4 bv = *(const float4*)(g_b23 + gcol);
            float v0 = sC[r * 132 + c4 + 0] + bv.x;
            float v1 = sC[r * 132 + c4 + 1] + bv.y;
            float v2 = sC[r * 132 + c4 + 2] + bv.z;
            float v3 = sC[r * 132 + c4 + 3] + bv.w;
            __nv_bfloat162 lo = __floats2bfloat162_rn(v0, v1);
            __nv_bfloat162 hi = __floats2bfloat162_rn(v2, v3);
            uint2 u;
            u.x = *reinterpret_cast<unsigned*>(&lo);
            u.y = *reinterpret_cast<unsigned*>(&hi);
            *(uint2*)(g_h3 + (size_t)grow * 256 + gcol) = u;
        }
    }
}

// ---------------- pipelined gemm5 (literal clone; N=1024, residual mix) --------
__global__ void __launch_bounds__(512, 2)
gemm5p_kernel(float* __restrict__ out, const float* __restrict__ x) {
    __shared__ __align__(16) char sm[SMEM_BYTES];
    bf16* sA = reinterpret_cast<bf16*>(sm);
    bf16* sB = reinterpret_cast<bf16*>(sm + 2 * AS2 * 2);
    uint32_t sA_u = (uint32_t)__cvta_generic_to_shared(sA);
    uint32_t sB_u = (uint32_t)__cvta_generic_to_shared(sB);

    int tid = threadIdx.x;
    int warp = tid >> 5;
    int mw = warp >> 2, nw = warp & 3;
    int row0 = blockIdx.y * 128;
    int col0 = blockIdx.x * 128;

    wmma::fragment<wmma::accumulator, 16, 16, 16, float> c[2][2];
    #pragma unroll
    for (int i = 0; i < 2; i++)
        #pragma unroll
        for (int j = 0; j < 2; j++) wmma::fill_fragment(c[i][j], 0.0f);

    int ar = tid >> 2, ac = (tid & 3) << 3;
    int br = tid >> 4, bc = (tid & 15) << 3;

    auto load_tile = [&](int stage, int k0) {
        cp16(sA_u + (stage * AS2 + ar * 40 + ac) * 2,
             g_h3 + (size_t)(row0 + ar) * 256 + k0 + ac);
        cp16(sB_u + (stage * BS2 + br * 136 + bc) * 2,
             g_Wu2 + (size_t)(k0 + br) * 1024 + col0 + bc);
        asm volatile("cp.async.commit_group;\n");
    };

    load_tile(0, 0);
    const int KT = 8;
    for (int kt = 0; kt < KT; kt++) {
        int cur = kt & 1;
        if (kt + 1 < KT) {
            load_tile(cur ^ 1, (kt + 1) * 32);
            asm volatile("cp.async.wait_group 1;\n");
        } else {
            asm volatile("cp.async.wait_group 0;\n");
        }
        __syncthreads();
        #pragma unroll
        for (int ks = 0; ks < 2; ks++) {
            wmma::fragment<wmma::matrix_a, 16, 16, 16, bf16, wmma::row_major> a0, a1;
            wmma::fragment<wmma::matrix_b, 16, 16, 16, bf16, wmma::row_major> b0, b1f;
            const bf16* pa = sA + cur * AS2 + (mw * 32) * 40 + ks * 16;
            wmma::load_matrix_sync(a0, pa, 40);
            wmma::load_matrix_sync(a1, pa + 16 * 40, 40);
            const bf16* pb = sB + cur * BS2 + (ks * 16) * 136 + nw * 32;
            wmma::load_matrix_sync(b0, pb, 136);
            wmma::load_matrix_sync(b1f, pb + 16, 136);
            wmma::mma_sync(c[0][0], a0, b0, c[0][0]);
            wmma::mma_sync(c[0][1], a0, b1f, c[0][1]);
            wmma::mma_sync(c[1][0], a1, b0, c[1][0]);
            wmma::mma_sync(c[1][1], a1, b1f, c[1][1]);
        }
        __syncthreads();
    }

    float* sC = reinterpret_cast<float*>(sm);
    #pragma unroll
    for (int i = 0; i < 2; i++) {
        __syncthreads();
        wmma::store_matrix_sync(sC + (mw * 16) * 132 + nw * 32,      c[i][0], 132, wmma::mem_row_major);
        wmma::store_matrix_sync(sC + (mw * 16) * 132 + nw * 32 + 16, c[i][1], 132, wmma::mem_row_major);
        __syncthreads();
        #pragma unroll
        for (int e = tid; e < 64 * 32; e += 512) {
            int r = e >> 5;
            int c4 = (e & 31) << 2;
            int grow = row0 + (r >> 4) * 32 + i * 16 + (r & 15);
            int gcol = col0 + c4;
            float4 bv = *(const float4*)(g_bu2 + gcol);
            float v0 = sC[r * 132 + c4 + 0] + bv.x;
            float v1 = sC[r * 132 + c4 + 1] + bv.y;
            float v2 = sC[r * 132 + c4 + 2] + bv.z;
            float v3 = sC[r * 132 + c4 + 3] + bv.w;
            float4 xv = *(const float4*)(x + (size_t)grow * 1024 + gcol);
            float4 o;
            o.x = 0.5f * v0 + 0.5f * xv.x;
            o.y = 0.5f * v1 + 0.5f * xv.y;
            o.z = 0.5f * v2 + 0.5f * xv.z;
            o.w = 0.5f * v3 + 0.5f * xv.w;
            *(float4*)(out + (size_t)grow * 1024 + gcol) = o;
        }
    }
}

// ---------------- launcher ----------------
extern "C" void kernel_launch(void* const* d_in, const int* in_sizes, int n_in,
                              void* d_out, int out_size) {
    const float* x    = (const float*)d_in[0];
    const float* ln_g = (const float*)d_in[1];
    const float* ln_b = (const float*)d_in[2];
    const float* Wd   = (const float*)d_in[3];
    const float* bd   = (const float*)d_in[4];
    const float* Wg   = (const float*)d_in[5];
    const float* bg   = (const float*)d_in[6];
    const float* dw_w = (const float*)d_in[7];
    const float* dw_b = (const float*)d_in[8];
    const float* W1   = (const float*)d_in[9];
    const float* b1   = (const float*)d_in[10];
    const float* W2   = (const float*)d_in[11];
    const float* b2   = (const float*)d_in[12];
    // d_in[13..16] = Wq,bq,Wk,bk : dead (softmax over a single key == 1)
    const float* Wv   = (const float*)d_in[17];
    const float* bv   = (const float*)d_in[18];
    const float* Wo   = (const float*)d_in[19];
    const float* bo   = (const float*)d_in[20];
    const float* Wu   = (const float*)d_in[21];
    const float* bu   = (const float*)d_in[22];
    const float* Wld  = (const float*)d_in[23];
    const float* Wlu  = (const float*)d_in[24];
    float* out = (float*)d_out;

    prep_wdg<<<(1024 * 512) / 256, 256>>>(Wd, Wg);                    // 1
    prep_bdg<<<1, 512>>>(bd, bg);                                     // 2
    ln_kernel<<<BB / 8, 256>>>(x, ln_g, ln_b);                        // 3
    gemm1s_glu_kernel<<<dim3(4, BB / 128), 512>>>(dw_w, dw_b);        // 4 (ncu slot)
    cvt_kernel<<<(256 * 256 + 255) / 256, 256>>>(W1, g_W1b, 256*256); // 5
    gemm2s_kernel<<<dim3(2, BB / 128), 512>>>(b1);                    // 6
    prep_wvo<<<64, 256>>>(Wv, Wo, bv, bo);                            // 7
    prep_w2vo<<<64, 256>>>(W2, b2);                                   // 8
    gemm3p_kernel<<<dim3(2, BB / 128), 512>>>();                      // 9
    prep_T<<<256, 256>>>(Wu, Wld);                                    // 10
    prep_wu2<<<dim3(256, 4), 256>>>(Wu, Wlu);                         // 11
    prep_bu2<<<1, 1024>>>(bu, Wld, Wlu);                              // 12
    gemm5p_kernel<<<dim3(8, BB / 128), 512>>>(out, x);                // 13 (clone)
}